// round 5
// baseline (speedup 1.0000x reference)
#include <cuda_runtime.h>
#include <cuda_bf16.h>
#include <math.h>

#define BATCH 2
#define T 1024
#define VOCAB 50304
#define E 768
#define L 12
#define H 12
#define HS 64
#define F4 3072
#define ROWS (BATCH * T)
#define BH (BATCH * H)

// ---------------- scratch ----------------
__device__ __align__(128) float          g_x   [ROWS * E];
__device__ __align__(128) __nv_bfloat16  g_xn3 [ROWS * 3 * E];
__device__ __align__(128) float          g_qkv [ROWS * 3 * E];
__device__ __align__(128) __nv_bfloat16  g_q3  [ROWS * 3 * E];
__device__ __align__(128) __nv_bfloat16  g_k3t [BH * 3 * HS * T];
__device__ __align__(128) __nv_bfloat16  g_v3  [BH * 3 * T * HS];
__device__ __align__(128) float          g_S   [(size_t)BH * T * T];
__device__ __align__(128) __nv_bfloat16  g_P3  [(size_t)BH * T * 3 * T];
__device__ __align__(128) __nv_bfloat16  g_att3[ROWS * 3 * E];
__device__ __align__(128) __nv_bfloat16  g_h3  [ROWS * 3 * F4];
__device__ __align__(128) __nv_bfloat16  g_w3  [3 * E * F4];
__device__ __align__(128) __nv_bfloat16  g_lm3 [(size_t)3 * E * VOCAB];

__device__ __forceinline__ unsigned smem_u32(const void* p) {
    unsigned a;
    asm("{ .reg .u64 t; cvta.to.shared.u64 t, %1; cvt.u32.u64 %0, t; }" : "=r"(a) : "l"(p));
    return a;
}
__device__ __forceinline__ void bsplit(float v, __nv_bfloat16& hi, __nv_bfloat16& lo) {
    hi = __float2bfloat16(v);
    lo = __float2bfloat16(v - __bfloat162float(hi));
}

// ---------------- bf16 mma.sync GEMM (v2: 1 sync/iter, frag double-buffer) ---
// C[M,N] = A[M,K3] @ B[K3,N]; K3 = 3K interleaved-64 bf16x3 split.
// mode 0: plain. mode 2: attention scores (z=b*H+h). mode 3: P @ V.
template<int BN, bool TOUT>
__global__ void __launch_bounds__(256, 1)
hgemm(const __nv_bfloat16* __restrict__ A, const __nv_bfloat16* __restrict__ Bm,
      const float* __restrict__ bias, const float* __restrict__ res,
      float* __restrict__ Cf, __nv_bfloat16* __restrict__ C3,
      int lda, int ldb, int ldc, int K3, int mode, int relu)
{
    constexpr int CHB   = BN / 8;            // 16B chunks per B smem row
    constexpr int CNTB  = (64 * CHB) / 256;  // B cp.async per thread per stage
    constexpr int ASTG  = 128 * 64 * 2;      // bytes per A stage
    constexpr int BSTG  = 64 * BN * 2;
    constexpr int WARPN = BN / 4;
    constexpr int NF    = WARPN / 8;

    const int m0 = blockIdx.x * 128, n0 = blockIdx.y * BN, z = blockIdx.z;
    if (mode == 2 && n0 > m0 + 127) return;

    extern __shared__ __nv_bfloat16 sm[];
    const unsigned Asb = smem_u32(sm);
    const unsigned Bsb = Asb + 3 * ASTG;

    size_t rowb; int colb;
    const __nv_bfloat16 *Ag, *Bg;
    if (mode == 2) {
        int b = z / H, h = z - b * H;
        Ag = A + (size_t)(b * T + m0) * lda + h * 192;
        Bg = Bm + (size_t)z * 192 * ldb + n0;
        rowb = (size_t)z * T + m0; colb = n0;
    } else if (mode == 3) {
        int b = z / H, h = z - b * H;
        Ag = A + (size_t)(z * T + m0) * lda;
        Bg = Bm + (size_t)z * 3 * T * ldb + n0;
        rowb = (size_t)(b * T + m0); colb = h * 64 + n0;
    } else {
        Ag = A + (size_t)m0 * lda;
        Bg = Bm + n0;
        rowb = m0; colb = n0;
    }

    int kt = K3 / 64;
    if (mode == 3) { int c = 3 * (m0 / 64 + 2); if (c < kt) kt = c; }

    const int tid = threadIdx.x;
    const int w = tid >> 5, l = tid & 31;
    const int wm = w >> 2, wn = w & 3;

    auto loadStage = [&](int tt, int s) {
        const __nv_bfloat16* ag = Ag + tt * 64;
        #pragma unroll
        for (int i = 0; i < 4; i++) {
            int id = tid * 4 + i;
            int r = id >> 3, c = id & 7;
            unsigned dst = Asb + s * ASTG + r * 128 + ((c ^ (r & 7)) << 4);
            const __nv_bfloat16* src = ag + (size_t)r * lda + c * 8;
            asm volatile("cp.async.cg.shared.global [%0], [%1], 16;" :: "r"(dst), "l"(src));
        }
        const __nv_bfloat16* bg = Bg + (size_t)tt * 64 * ldb;
        #pragma unroll
        for (int i = 0; i < CNTB; i++) {
            int id = tid * CNTB + i;
            int r = id / CHB, c = id % CHB;
            unsigned dst = Bsb + s * BSTG + r * (BN * 2) + ((c ^ (r & 7)) << 4);
            const __nv_bfloat16* src = bg + (size_t)r * ldb + c * 8;
            asm volatile("cp.async.cg.shared.global [%0], [%1], 16;" :: "r"(dst), "l"(src));
        }
    };

    if (0 < kt) loadStage(0, 0);
    asm volatile("cp.async.commit_group;");
    if (1 < kt) loadStage(1, 1);
    asm volatile("cp.async.commit_group;");

    float acc[4][NF][4] = {};

    for (int t = 0; t < kt; t++) {
        asm volatile("cp.async.wait_group 1;");
        __syncthreads();
        if (t + 2 < kt) loadStage(t + 2, (t + 2) % 3);
        asm volatile("cp.async.commit_group;");

        const unsigned as = Asb + (t % 3) * ASTG;
        const unsigned bs = Bsb + (t % 3) * BSTG;

        unsigned fa[2][4][4], fb[2][NF][2];

        auto ldA = [&](int kk, unsigned f[4][4]) {
            #pragma unroll
            for (int i = 0; i < 4; i++) {
                int row = wm * 64 + i * 16 + (l & 15);
                int ch  = kk * 2 + (l >> 4);
                unsigned ad = as + row * 128 + ((ch ^ (row & 7)) << 4);
                asm volatile("ldmatrix.sync.aligned.m8n8.x4.shared.b16 {%0,%1,%2,%3}, [%4];"
                    : "=r"(f[i][0]), "=r"(f[i][1]), "=r"(f[i][2]), "=r"(f[i][3]) : "r"(ad));
            }
        };
        auto ldB = [&](int kk, unsigned f[NF][2]) {
            #pragma unroll
            for (int p = 0; p < NF / 2; p++) {
                int row = kk * 16 + (l & 15);
                int ch  = wn * NF + p * 2 + (l >> 4);
                unsigned bd = bs + row * (BN * 2) + ((ch ^ (row & 7)) << 4);
                unsigned r0, r1, r2, r3;
                asm volatile("ldmatrix.sync.aligned.m8n8.x4.trans.shared.b16 {%0,%1,%2,%3}, [%4];"
                    : "=r"(r0), "=r"(r1), "=r"(r2), "=r"(r3) : "r"(bd));
                f[2*p][0] = r0; f[2*p][1] = r1; f[2*p+1][0] = r2; f[2*p+1][1] = r3;
            }
        };

        ldA(0, fa[0]); ldB(0, fb[0]);
        #pragma unroll
        for (int kk = 0; kk < 4; kk++) {
            if (kk < 3) { ldA(kk + 1, fa[(kk + 1) & 1]); ldB(kk + 1, fb[(kk + 1) & 1]); }
            #pragma unroll
            for (int i = 0; i < 4; i++)
                #pragma unroll
                for (int j = 0; j < NF; j++)
                    asm volatile(
                        "mma.sync.aligned.m16n8k16.row.col.f32.bf16.bf16.f32 "
                        "{%0,%1,%2,%3}, {%4,%5,%6,%7}, {%8,%9}, {%0,%1,%2,%3};"
                        : "+f"(acc[i][j][0]), "+f"(acc[i][j][1]),
                          "+f"(acc[i][j][2]), "+f"(acc[i][j][3])
                        : "r"(fa[kk & 1][i][0]), "r"(fa[kk & 1][i][1]),
                          "r"(fa[kk & 1][i][2]), "r"(fa[kk & 1][i][3]),
                          "r"(fb[kk & 1][j][0]), "r"(fb[kk & 1][j][1]));
        }
    }

    // epilogue
    #pragma unroll
    for (int i = 0; i < 4; i++) {
        #pragma unroll
        for (int j = 0; j < NF; j++) {
            #pragma unroll
            for (int half = 0; half < 2; half++) {
                int rr = wm * 64 + i * 16 + (l >> 2) + half * 8;
                int c  = wn * WARPN + j * 8 + (l & 3) * 2;
                int cg = colb + c;
                float v0 = acc[i][j][half * 2 + 0];
                float v1 = acc[i][j][half * 2 + 1];
                size_t ro = rowb + rr;
                if (bias) { v0 += bias[cg]; v1 += bias[cg + 1]; }
                if (res)  { v0 += res[ro * ldc + cg]; v1 += res[ro * ldc + cg + 1]; }
                if (relu) { v0 = fmaxf(v0, 0.f); v1 = fmaxf(v1, 0.f); }
                if (TOUT) {
                    int kb = cg >> 6, kr = cg & 63;
                    size_t base = ro * ldc + 192 * kb + kr;
                    __nv_bfloat16 h0, l0, h1, l1;
                    bsplit(v0, h0, l0); bsplit(v1, h1, l1);
                    C3[base]       = h0; C3[base + 1]   = h1;
                    C3[base + 64]  = l0; C3[base + 65]  = l1;
                    C3[base + 128] = h0; C3[base + 129] = h1;
                } else {
                    Cf[ro * ldc + cg]     = v0;
                    Cf[ro * ldc + cg + 1] = v1;
                }
            }
        }
    }
}

// ---------------- small kernels ----------------
__global__ void embed_kernel(const int* __restrict__ idx, const float* __restrict__ te,
                             const float* __restrict__ pe, float* __restrict__ x)
{
    int row = blockIdx.x, t = row % T, tok = idx[row];
    const float* a = te + (size_t)tok * E;
    const float* b = pe + (size_t)t * E;
    float* xr = x + (size_t)row * E;
    for (int i = threadIdx.x; i < E; i += blockDim.x) xr[i] = a[i] + b[i];
}

__global__ __launch_bounds__(256)
void layernorm_kernel(const float* __restrict__ x, const float* __restrict__ g,
                      const float* __restrict__ b, __nv_bfloat16* __restrict__ y3)
{
    int row = blockIdx.x, tid = threadIdx.x;
    const float* xr = x + (size_t)row * E;
    float s = 0.f, s2 = 0.f;
    for (int i = tid; i < E; i += 256) { float v = xr[i]; s += v; s2 += v * v; }
    #pragma unroll
    for (int o = 16; o > 0; o >>= 1) {
        s += __shfl_down_sync(~0u, s, o); s2 += __shfl_down_sync(~0u, s2, o);
    }
    __shared__ float ws[8], ws2[8];
    if ((tid & 31) == 0) { ws[tid >> 5] = s; ws2[tid >> 5] = s2; }
    __syncthreads();
    if (tid == 0) {
        float a = 0.f, a2 = 0.f;
        #pragma unroll
        for (int i = 0; i < 8; i++) { a += ws[i]; a2 += ws2[i]; }
        ws[0] = a; ws2[0] = a2;
    }
    __syncthreads();
    float mean = ws[0] / E, var = ws2[0] / E - mean * mean;
    float inv = rsqrtf(var + 1e-5f);
    for (int i = tid; i < E; i += 256) {
        float v = (xr[i] - mean) * inv * g[i] + b[i];
        __nv_bfloat16 hi, lo; bsplit(v, hi, lo);
        size_t base = (size_t)row * (3 * E) + 192 * (i >> 6) + (i & 63);
        y3[base] = hi; y3[base + 64] = lo; y3[base + 128] = hi;
    }
}

// fp32 W[K,N] -> bf16 W3[3K,N] interleaved (B-side: hi,hi,lo)
__global__ void wsplit_kernel(const float* __restrict__ src, __nv_bfloat16* __restrict__ dst,
                              int N, int dstLD, int colOff)
{
    size_t i = (size_t)blockIdx.x * 256 + threadIdx.x;
    int n = (int)(i % N), k = (int)(i / N);
    float v = src[i];
    __nv_bfloat16 hi, lo; bsplit(v, hi, lo);
    size_t rb = (size_t)(192 * (k >> 6) + (k & 63)) * dstLD + colOff + n;
    dst[rb] = hi; dst[rb + (size_t)64 * dstLD] = hi; dst[rb + (size_t)128 * dstLD] = lo;
}

// fused q/k/v weight split (z selects source, colOff = z*E)
__global__ void wsplit3_kernel(const float* __restrict__ s0, const float* __restrict__ s1,
                               const float* __restrict__ s2, __nv_bfloat16* __restrict__ dst)
{
    int z = blockIdx.y;
    const float* src = (z == 0) ? s0 : (z == 1) ? s1 : s2;
    size_t i = (size_t)blockIdx.x * 256 + threadIdx.x;  // over E*E
    int n = (int)(i % E), k = (int)(i / E);
    float v = src[i];
    __nv_bfloat16 hi, lo; bsplit(v, hi, lo);
    size_t rb = (size_t)(192 * (k >> 6) + (k & 63)) * (3 * E) + z * E + n;
    dst[rb] = hi; dst[rb + (size_t)64 * 3 * E] = hi; dst[rb + (size_t)128 * 3 * E] = lo;
}

// q cols of qkv -> q3 (A-side: hi,lo,hi)
__global__ void qpack_kernel(const float* __restrict__ qkv, __nv_bfloat16* __restrict__ q3)
{
    size_t i = (size_t)blockIdx.x * 256 + threadIdx.x;
    int c = (int)(i % E); size_t row = i / E;
    float v = qkv[row * (3 * E) + c];
    __nv_bfloat16 hi, lo; bsplit(v, hi, lo);
    size_t base = row * (3 * E) + (c >> 6) * 192 + (c & 63);
    q3[base] = hi; q3[base + 64] = lo; q3[base + 128] = hi;
}

// k cols -> k3t [z][192][T] transposed (B-side: hi,hi,lo)
__global__ void kpackT_kernel(const float* __restrict__ qkv, __nv_bfloat16* __restrict__ k3t)
{
    __shared__ float tile[32][33];
    int z = blockIdx.z, b = z / H, h = z - b * H;
    int t0 = blockIdx.x * 32, d0 = blockIdx.y * 32;
    int tx = threadIdx.x, ty = threadIdx.y;
    for (int i = ty; i < 32; i += 8)
        tile[i][tx] = qkv[(size_t)(b * T + t0 + i) * (3 * E) + E + h * 64 + d0 + tx];
    __syncthreads();
    for (int i = ty; i < 32; i += 8) {
        float v = tile[tx][i];
        __nv_bfloat16 hi, lo; bsplit(v, hi, lo);
        size_t rb = ((size_t)z * 192 + d0 + i) * T + t0 + tx;
        k3t[rb] = hi; k3t[rb + (size_t)64 * T] = hi; k3t[rb + (size_t)128 * T] = lo;
    }
}

// v cols -> v3 [z][3T][64] (B-side rows over K=T: hi,hi,lo)
__global__ void vpack_kernel(const float* __restrict__ qkv, __nv_bfloat16* __restrict__ v3)
{
    int z = blockIdx.y, b = z / H, h = z - b * H;
    int t = blockIdx.x * 4 + threadIdx.y;
    int d = threadIdx.x;
    float v = qkv[(size_t)(b * T + t) * (3 * E) + 2 * E + h * 64 + d];
    __nv_bfloat16 hi, lo; bsplit(v, hi, lo);
    size_t rb = ((size_t)z * 3 * T + 192 * (t >> 6) + (t & 63)) * 64 + d;
    v3[rb] = hi; v3[rb + 64 * 64] = hi; v3[rb + 128 * 64] = lo;
}

__global__ __launch_bounds__(128)
void softmax_kernel(const float* __restrict__ S, __nv_bfloat16* __restrict__ P3)
{
    int bid = blockIdx.x, z = bid >> 10, qi = bid & 1023, tid = threadIdx.x;
    const float* srow = S + ((size_t)z << 20) + ((size_t)qi << 10);
    __nv_bfloat16* prow = P3 + ((size_t)(z << 10) + qi) * (3 * T);
    __shared__ float sc[T];
    __shared__ float red[128];
    float lmax = -1e30f;
    for (int j = tid; j <= qi; j += 128) {
        float e = srow[j] * 0.125f;
        sc[j] = e; lmax = fmaxf(lmax, e);
    }
    red[tid] = lmax; __syncthreads();
    #pragma unroll
    for (int st = 64; st > 0; st >>= 1) {
        if (tid < st) red[tid] = fmaxf(red[tid], red[tid + st]);
        __syncthreads();
    }
    float m = red[0]; __syncthreads();
    float lsum = 0.f;
    for (int j = tid; j <= qi; j += 128) { float e = __expf(sc[j] - m); sc[j] = e; lsum += e; }
    red[tid] = lsum; __syncthreads();
    #pragma unroll
    for (int st = 64; st > 0; st >>= 1) {
        if (tid < st) red[tid] += red[tid + st];
        __syncthreads();
    }
    float inv = 1.f / red[0]; __syncthreads();
    // only the K-range the PV GEMM actually reads: 3 * (tile_m0 + 128)
    int end3 = 3 * ((qi & ~127) + 128);
    for (int j = tid; j < end3; j += 128) {
        int kb = j / 192, rr = j - kb * 192;
        int k = kb * 64 + (rr & 63);
        float p = (k <= qi) ? sc[k] * inv : 0.f;
        __nv_bfloat16 o;
        if ((rr >> 6) == 1) {
            __nv_bfloat16 hi = __float2bfloat16(p);
            o = __float2bfloat16(p - __bfloat162float(hi));
        } else o = __float2bfloat16(p);
        prow[j] = o;
    }
}

// ---------------- host ----------------
#define ASTGB (128 * 64 * 2)
#define SMEMN(BN) (3 * (ASTGB + 64 * (BN) * 2))

extern "C" void kernel_launch(void* const* d_in, const int* in_sizes, int n_in,
                              void* d_out, int out_size)
{
    const int*   idx     = (const int*)  d_in[0];
    const float* tok_emb = (const float*)d_in[1];
    const float* pos_emb = (const float*)d_in[2];
    const float* wq      = (const float*)d_in[3];
    const float* wk      = (const float*)d_in[4];
    const float* wv      = (const float*)d_in[5];
    const float* wproj   = (const float*)d_in[6];
    const float* bproj   = (const float*)d_in[7];
    const float* ln1_g   = (const float*)d_in[8];
    const float* ln1_b   = (const float*)d_in[9];
    const float* ln2_g   = (const float*)d_in[10];
    const float* ln2_b   = (const float*)d_in[11];
    const float* wfc     = (const float*)d_in[12];
    const float* bfc     = (const float*)d_in[13];
    const float* wpr2    = (const float*)d_in[14];
    const float* bpr2    = (const float*)d_in[15];
    const float* lnf_g   = (const float*)d_in[16];
    const float* lnf_b   = (const float*)d_in[17];
    const float* lm_w    = (const float*)d_in[18];
    const float* lm_b    = (const float*)d_in[19];
    float* out = (float*)d_out;

    cudaFuncSetAttribute(hgemm<256, false>, cudaFuncAttributeMaxDynamicSharedMemorySize, SMEMN(256));
    cudaFuncSetAttribute(hgemm<256, true>,  cudaFuncAttributeMaxDynamicSharedMemorySize, SMEMN(256));
    cudaFuncSetAttribute(hgemm<192, false>, cudaFuncAttributeMaxDynamicSharedMemorySize, SMEMN(192));
    cudaFuncSetAttribute(hgemm<128, false>, cudaFuncAttributeMaxDynamicSharedMemorySize, SMEMN(128));
    cudaFuncSetAttribute(hgemm<64,  true>,  cudaFuncAttributeMaxDynamicSharedMemorySize, SMEMN(64));

    float *x, *qkv, *S;
    __nv_bfloat16 *xn3, *q3, *k3t, *v3, *P3, *att3, *h3, *w3, *lm3;
    cudaGetSymbolAddress((void**)&x, g_x);     cudaGetSymbolAddress((void**)&xn3, g_xn3);
    cudaGetSymbolAddress((void**)&qkv, g_qkv); cudaGetSymbolAddress((void**)&q3, g_q3);
    cudaGetSymbolAddress((void**)&k3t, g_k3t); cudaGetSymbolAddress((void**)&v3, g_v3);
    cudaGetSymbolAddress((void**)&S, g_S);     cudaGetSymbolAddress((void**)&P3, g_P3);
    cudaGetSymbolAddress((void**)&att3, g_att3); cudaGetSymbolAddress((void**)&h3, g_h3);
    cudaGetSymbolAddress((void**)&w3, g_w3);   cudaGetSymbolAddress((void**)&lm3, g_lm3);

    dim3 tb(32, 8);
    embed_kernel<<<ROWS, 256>>>(idx, tok_emb, pos_emb, x);

    for (int l = 0; l < L; l++) {
        const float* wq_l  = wq  + (size_t)l * E * E;
        const float* wk_l  = wk  + (size_t)l * E * E;
        const float* wv_l  = wv  + (size_t)l * E * E;
        const float* wp_l  = wproj + (size_t)l * E * E;
        const float* wfc_l = wfc + (size_t)l * E * F4;
        const float* wp2_l = wpr2 + (size_t)l * F4 * E;

        layernorm_kernel<<<ROWS, 256>>>(x, ln1_g + l * E, ln1_b + l * E, xn3);

        wsplit3_kernel<<<dim3(E * E / 256, 3), 256>>>(wq_l, wk_l, wv_l, w3);
        hgemm<256, false><<<dim3(16, 9, 1), 256, SMEMN(256)>>>(
            xn3, w3, nullptr, nullptr, qkv, nullptr, 3 * E, 3 * E, 3 * E, 3 * E, 0, 0);

        qpack_kernel<<<ROWS * E / 256, 256>>>(qkv, q3);
        kpackT_kernel<<<dim3(32, 2, BH), tb>>>(qkv, k3t);
        vpack_kernel<<<dim3(T / 4, BH), dim3(64, 4)>>>(qkv, v3);

        hgemm<128, false><<<dim3(8, 8, BH), 256, SMEMN(128)>>>(
            q3, k3t, nullptr, nullptr, S, nullptr, 3 * E, T, T, 192, 2, 0);
        softmax_kernel<<<BH * T, 128>>>(S, P3);
        hgemm<64, true><<<dim3(8, 1, BH), 256, SMEMN(64)>>>(
            P3, v3, nullptr, nullptr, nullptr, att3, 3 * T, HS, 3 * E, 3 * T, 3, 0);

        wsplit_kernel<<<E * E / 256, 256>>>(wp_l, w3, E, E, 0);
        hgemm<128, false><<<dim3(16, 6, 1), 256, SMEMN(128)>>>(
            att3, w3, bproj + l * E, x, x, nullptr, 3 * E, E, E, 3 * E, 0, 0);

        layernorm_kernel<<<ROWS, 256>>>(x, ln2_g + l * E, ln2_b + l * E, xn3);
        wsplit_kernel<<<E * F4 / 256, 256>>>(wfc_l, w3, F4, F4, 0);
        hgemm<256, true><<<dim3(16, 12, 1), 256, SMEMN(256)>>>(
            xn3, w3, bfc + (size_t)l * F4, nullptr, nullptr, h3, 3 * E, F4, 3 * F4, 3 * E, 0, 1);
        wsplit_kernel<<<F4 * E / 256, 256>>>(wp2_l, w3, E, E, 0);
        hgemm<128, false><<<dim3(16, 6, 1), 256, SMEMN(128)>>>(
            h3, w3, bpr2 + l * E, x, x, nullptr, 3 * F4, E, E, 3 * F4, 0, 0);
    }

    layernorm_kernel<<<ROWS, 256>>>(x, lnf_g, lnf_b, xn3);
    wsplit_kernel<<<E * VOCAB / 256, 256>>>(lm_w, lm3, VOCAB, VOCAB, 0);
    hgemm<192, false><<<dim3(16, VOCAB / 192, 1), 256, SMEMN(192)>>>(
        xn3, lm3, lm_b, nullptr, out, nullptr, 3 * E, VOCAB, VOCAB, 3 * E, 0, 0);
}

// round 6
// speedup vs baseline: 1.4660x; 1.4660x over previous
#include <cuda_runtime.h>
#include <cuda_bf16.h>
#include <math.h>

#define BATCH 2
#define T 1024
#define VOCAB 50304
#define E 768
#define L 12
#define H 12
#define HS 64
#define F4 3072
#define ROWS (BATCH * T)
#define BH (BATCH * H)

// ---------------- scratch ----------------
__device__ __align__(128) float          g_x   [ROWS * E];
__device__ __align__(128) __nv_bfloat16  g_xn3 [ROWS * 3 * E];
__device__ __align__(128) float          g_qkv [ROWS * 3 * E];
__device__ __align__(128) __nv_bfloat16  g_q3  [ROWS * 3 * E];
__device__ __align__(128) __nv_bfloat16  g_k3t [BH * 3 * HS * T];
__device__ __align__(128) __nv_bfloat16  g_v3  [BH * 3 * T * HS];
__device__ __align__(128) float          g_S   [(size_t)BH * T * T];
__device__ __align__(128) __nv_bfloat16  g_P3  [(size_t)BH * T * 3 * T];
__device__ __align__(128) __nv_bfloat16  g_att3[ROWS * 3 * E];
__device__ __align__(128) __nv_bfloat16  g_h3  [ROWS * 3 * F4];
__device__ __align__(128) __nv_bfloat16  g_w3  [3 * E * F4];
__device__ __align__(128) __nv_bfloat16  g_lm3 [(size_t)3 * E * VOCAB];

__device__ __forceinline__ unsigned smem_u32(const void* p) {
    unsigned a;
    asm("{ .reg .u64 t; cvta.to.shared.u64 t, %1; cvt.u32.u64 %0, t; }" : "=r"(a) : "l"(p));
    return a;
}
__device__ __forceinline__ void bsplit(float v, __nv_bfloat16& hi, __nv_bfloat16& lo) {
    hi = __float2bfloat16(v);
    lo = __float2bfloat16(v - __bfloat162float(hi));
}

// ---------------- bf16 mma.sync GEMM v3 ----------------
// 128-thread CTA, 4 warps (2x2), warp tile 64 x (BN/2). 3-stage cp.async.
// 2 CTAs/SM resident. K3 = 3K interleaved-64 bf16x3 split.
// mode 0: plain. mode 2: attention scores (z=b*H+h). mode 3: P @ V.
template<int BN, bool TOUT>
__global__ void __launch_bounds__(128, 2)
hgemm(const __nv_bfloat16* __restrict__ A, const __nv_bfloat16* __restrict__ Bm,
      const float* __restrict__ bias, const float* __restrict__ res,
      float* __restrict__ Cf, __nv_bfloat16* __restrict__ C3,
      int lda, int ldb, int ldc, int K3, int mode, int relu)
{
    constexpr int CHB   = BN / 8;             // 16B chunks per B smem row
    constexpr int CNTB  = (64 * CHB) / 128;   // B cp.async per thread
    constexpr int ASTG  = 128 * 64 * 2;       // bytes per A stage
    constexpr int BSTG  = 64 * BN * 2;
    constexpr int WARPN = BN / 2;             // warp tile N
    constexpr int NF    = WARPN / 8;

    const int m0 = blockIdx.x * 128, n0 = blockIdx.y * BN, z = blockIdx.z;
    if (mode == 2 && n0 > m0 + 127) return;

    extern __shared__ __nv_bfloat16 sm[];
    const unsigned Asb = smem_u32(sm);
    const unsigned Bsb = Asb + 3 * ASTG;

    size_t rowb; int colb;
    const __nv_bfloat16 *Ag, *Bg;
    if (mode == 2) {
        int b = z / H, h = z - b * H;
        Ag = A + (size_t)(b * T + m0) * lda + h * 192;
        Bg = Bm + (size_t)z * 192 * ldb + n0;
        rowb = (size_t)z * T + m0; colb = n0;
    } else if (mode == 3) {
        int b = z / H, h = z - b * H;
        Ag = A + (size_t)(z * T + m0) * lda;
        Bg = Bm + (size_t)z * 3 * T * ldb + n0;
        rowb = (size_t)(b * T + m0); colb = h * 64 + n0;
    } else {
        Ag = A + (size_t)m0 * lda;
        Bg = Bm + n0;
        rowb = m0; colb = n0;
    }

    int kt = K3 / 64;
    if (mode == 3) { int c = 3 * (m0 / 64 + 2); if (c < kt) kt = c; }

    const int tid = threadIdx.x;
    const int w = tid >> 5, l = tid & 31;
    const int wm = w >> 1, wn = w & 1;

    auto loadStage = [&](int tt, int s) {
        const __nv_bfloat16* ag = Ag + tt * 64;
        #pragma unroll
        for (int i = 0; i < 8; i++) {
            int id = i * 128 + tid;          // coalesced: consecutive tid -> consecutive 16B
            int r = id >> 3, c = id & 7;
            unsigned dst = Asb + s * ASTG + r * 128 + ((c ^ (r & 7)) << 4);
            const __nv_bfloat16* src = ag + (size_t)r * lda + c * 8;
            asm volatile("cp.async.cg.shared.global [%0], [%1], 16;" :: "r"(dst), "l"(src));
        }
        const __nv_bfloat16* bg = Bg + (size_t)tt * 64 * ldb;
        #pragma unroll
        for (int i = 0; i < CNTB; i++) {
            int id = i * 128 + tid;
            int r = id / CHB, c = id % CHB;
            unsigned dst = Bsb + s * BSTG + r * (BN * 2) + ((c ^ (r & 7)) << 4);
            const __nv_bfloat16* src = bg + (size_t)r * ldb + c * 8;
            asm volatile("cp.async.cg.shared.global [%0], [%1], 16;" :: "r"(dst), "l"(src));
        }
    };

    if (0 < kt) loadStage(0, 0);
    asm volatile("cp.async.commit_group;");
    if (1 < kt) loadStage(1, 1);
    asm volatile("cp.async.commit_group;");

    float acc[4][NF][4] = {};

    for (int t = 0; t < kt; t++) {
        asm volatile("cp.async.wait_group 1;");
        __syncthreads();
        if (t + 2 < kt) loadStage(t + 2, (t + 2) % 3);
        asm volatile("cp.async.commit_group;");

        const unsigned as = Asb + (t % 3) * ASTG;
        const unsigned bs = Bsb + (t % 3) * BSTG;

        #pragma unroll
        for (int kk = 0; kk < 4; kk++) {
            unsigned fa[4][4], fb[NF][2];
            #pragma unroll
            for (int i = 0; i < 4; i++) {
                int row = wm * 64 + i * 16 + (l & 15);
                int ch  = kk * 2 + (l >> 4);
                unsigned ad = as + row * 128 + ((ch ^ (row & 7)) << 4);
                asm volatile("ldmatrix.sync.aligned.m8n8.x4.shared.b16 {%0,%1,%2,%3}, [%4];"
                    : "=r"(fa[i][0]), "=r"(fa[i][1]), "=r"(fa[i][2]), "=r"(fa[i][3]) : "r"(ad));
            }
            #pragma unroll
            for (int p = 0; p < NF / 2; p++) {
                int row = kk * 16 + (l & 15);
                int ch  = wn * NF + p * 2 + (l >> 4);
                unsigned bd = bs + row * (BN * 2) + ((ch ^ (row & 7)) << 4);
                unsigned r0, r1, r2, r3;
                asm volatile("ldmatrix.sync.aligned.m8n8.x4.trans.shared.b16 {%0,%1,%2,%3}, [%4];"
                    : "=r"(r0), "=r"(r1), "=r"(r2), "=r"(r3) : "r"(bd));
                fb[2*p][0] = r0; fb[2*p][1] = r1; fb[2*p+1][0] = r2; fb[2*p+1][1] = r3;
            }
            #pragma unroll
            for (int i = 0; i < 4; i++)
                #pragma unroll
                for (int j = 0; j < NF; j++)
                    asm volatile(
                        "mma.sync.aligned.m16n8k16.row.col.f32.bf16.bf16.f32 "
                        "{%0,%1,%2,%3}, {%4,%5,%6,%7}, {%8,%9}, {%0,%1,%2,%3};"
                        : "+f"(acc[i][j][0]), "+f"(acc[i][j][1]),
                          "+f"(acc[i][j][2]), "+f"(acc[i][j][3])
                        : "r"(fa[i][0]), "r"(fa[i][1]), "r"(fa[i][2]), "r"(fa[i][3]),
                          "r"(fb[j][0]), "r"(fb[j][1]));
        }
        __syncthreads();
    }

    // epilogue
    #pragma unroll
    for (int i = 0; i < 4; i++) {
        #pragma unroll
        for (int j = 0; j < NF; j++) {
            #pragma unroll
            for (int half = 0; half < 2; half++) {
                int rr = wm * 64 + i * 16 + (l >> 2) + half * 8;
                int c  = wn * WARPN + j * 8 + (l & 3) * 2;
                int cg = colb + c;
                float v0 = acc[i][j][half * 2 + 0];
                float v1 = acc[i][j][half * 2 + 1];
                size_t ro = rowb + rr;
                if (bias) { v0 += bias[cg]; v1 += bias[cg + 1]; }
                if (res)  { v0 += res[ro * ldc + cg]; v1 += res[ro * ldc + cg + 1]; }
                if (relu) { v0 = fmaxf(v0, 0.f); v1 = fmaxf(v1, 0.f); }
                if (TOUT) {
                    int kb = cg >> 6, kr = cg & 63;
                    size_t base = ro * ldc + 192 * kb + kr;
                    __nv_bfloat16 h0, l0, h1, l1;
                    bsplit(v0, h0, l0); bsplit(v1, h1, l1);
                    C3[base]       = h0; C3[base + 1]   = h1;
                    C3[base + 64]  = l0; C3[base + 65]  = l1;
                    C3[base + 128] = h0; C3[base + 129] = h1;
                } else {
                    Cf[ro * ldc + cg]     = v0;
                    Cf[ro * ldc + cg + 1] = v1;
                }
            }
        }
    }
}

// ---------------- small kernels ----------------
__global__ void embed_kernel(const int* __restrict__ idx, const float* __restrict__ te,
                             const float* __restrict__ pe, float* __restrict__ x)
{
    int row = blockIdx.x, t = row % T, tok = idx[row];
    const float* a = te + (size_t)tok * E;
    const float* b = pe + (size_t)t * E;
    float* xr = x + (size_t)row * E;
    for (int i = threadIdx.x; i < E; i += blockDim.x) xr[i] = a[i] + b[i];
}

__global__ __launch_bounds__(256)
void layernorm_kernel(const float* __restrict__ x, const float* __restrict__ g,
                      const float* __restrict__ b, __nv_bfloat16* __restrict__ y3)
{
    int row = blockIdx.x, tid = threadIdx.x;
    const float* xr = x + (size_t)row * E;
    float s = 0.f, s2 = 0.f;
    for (int i = tid; i < E; i += 256) { float v = xr[i]; s += v; s2 += v * v; }
    #pragma unroll
    for (int o = 16; o > 0; o >>= 1) {
        s += __shfl_down_sync(~0u, s, o); s2 += __shfl_down_sync(~0u, s2, o);
    }
    __shared__ float ws[8], ws2[8];
    if ((tid & 31) == 0) { ws[tid >> 5] = s; ws2[tid >> 5] = s2; }
    __syncthreads();
    if (tid == 0) {
        float a = 0.f, a2 = 0.f;
        #pragma unroll
        for (int i = 0; i < 8; i++) { a += ws[i]; a2 += ws2[i]; }
        ws[0] = a; ws2[0] = a2;
    }
    __syncthreads();
    float mean = ws[0] / E, var = ws2[0] / E - mean * mean;
    float inv = rsqrtf(var + 1e-5f);
    for (int i = tid; i < E; i += 256) {
        float v = (xr[i] - mean) * inv * g[i] + b[i];
        __nv_bfloat16 hi, lo; bsplit(v, hi, lo);
        size_t base = (size_t)row * (3 * E) + 192 * (i >> 6) + (i & 63);
        y3[base] = hi; y3[base + 64] = lo; y3[base + 128] = hi;
    }
}

// fp32 W[K,N] -> bf16 W3[3K,N] interleaved (B-side: hi,hi,lo)
__global__ void wsplit_kernel(const float* __restrict__ src, __nv_bfloat16* __restrict__ dst,
                              int N, int dstLD, int colOff)
{
    size_t i = (size_t)blockIdx.x * 256 + threadIdx.x;
    int n = (int)(i % N), k = (int)(i / N);
    float v = src[i];
    __nv_bfloat16 hi, lo; bsplit(v, hi, lo);
    size_t rb = (size_t)(192 * (k >> 6) + (k & 63)) * dstLD + colOff + n;
    dst[rb] = hi; dst[rb + (size_t)64 * dstLD] = hi; dst[rb + (size_t)128 * dstLD] = lo;
}

// fused q/k/v weight split
__global__ void wsplit3_kernel(const float* __restrict__ s0, const float* __restrict__ s1,
                               const float* __restrict__ s2, __nv_bfloat16* __restrict__ dst)
{
    int z = blockIdx.y;
    const float* src = (z == 0) ? s0 : (z == 1) ? s1 : s2;
    size_t i = (size_t)blockIdx.x * 256 + threadIdx.x;
    int n = (int)(i % E), k = (int)(i / E);
    float v = src[i];
    __nv_bfloat16 hi, lo; bsplit(v, hi, lo);
    size_t rb = (size_t)(192 * (k >> 6) + (k & 63)) * (3 * E) + z * E + n;
    dst[rb] = hi; dst[rb + (size_t)64 * 3 * E] = hi; dst[rb + (size_t)128 * 3 * E] = lo;
}

// q cols of qkv -> q3 (A-side: hi,lo,hi)
__global__ void qpack_kernel(const float* __restrict__ qkv, __nv_bfloat16* __restrict__ q3)
{
    size_t i = (size_t)blockIdx.x * 256 + threadIdx.x;
    int c = (int)(i % E); size_t row = i / E;
    float v = qkv[row * (3 * E) + c];
    __nv_bfloat16 hi, lo; bsplit(v, hi, lo);
    size_t base = row * (3 * E) + (c >> 6) * 192 + (c & 63);
    q3[base] = hi; q3[base + 64] = lo; q3[base + 128] = hi;
}

// k cols -> k3t [z][192][T] transposed (B-side: hi,hi,lo)
__global__ void kpackT_kernel(const float* __restrict__ qkv, __nv_bfloat16* __restrict__ k3t)
{
    __shared__ float tile[32][33];
    int z = blockIdx.z, b = z / H, h = z - b * H;
    int t0 = blockIdx.x * 32, d0 = blockIdx.y * 32;
    int tx = threadIdx.x, ty = threadIdx.y;
    for (int i = ty; i < 32; i += 8)
        tile[i][tx] = qkv[(size_t)(b * T + t0 + i) * (3 * E) + E + h * 64 + d0 + tx];
    __syncthreads();
    for (int i = ty; i < 32; i += 8) {
        float v = tile[tx][i];
        __nv_bfloat16 hi, lo; bsplit(v, hi, lo);
        size_t rb = ((size_t)z * 192 + d0 + i) * T + t0 + tx;
        k3t[rb] = hi; k3t[rb + (size_t)64 * T] = hi; k3t[rb + (size_t)128 * T] = lo;
    }
}

// v cols -> v3 [z][3T][64] (B-side rows over K=T: hi,hi,lo)
__global__ void vpack_kernel(const float* __restrict__ qkv, __nv_bfloat16* __restrict__ v3)
{
    int z = blockIdx.y, b = z / H, h = z - b * H;
    int t = blockIdx.x * 4 + threadIdx.y;
    int d = threadIdx.x;
    float v = qkv[(size_t)(b * T + t) * (3 * E) + 2 * E + h * 64 + d];
    __nv_bfloat16 hi, lo; bsplit(v, hi, lo);
    size_t rb = ((size_t)z * 3 * T + 192 * (t >> 6) + (t & 63)) * 64 + d;
    v3[rb] = hi; v3[rb + 64 * 64] = hi; v3[rb + 128 * 64] = lo;
}

__global__ __launch_bounds__(128)
void softmax_kernel(const float* __restrict__ S, __nv_bfloat16* __restrict__ P3)
{
    int bid = blockIdx.x, z = bid >> 10, qi = bid & 1023, tid = threadIdx.x;
    const float* srow = S + ((size_t)z << 20) + ((size_t)qi << 10);
    __nv_bfloat16* prow = P3 + ((size_t)(z << 10) + qi) * (3 * T);
    __shared__ float sc[T];
    __shared__ float red[128];
    float lmax = -1e30f;
    for (int j = tid; j <= qi; j += 128) {
        float e = srow[j] * 0.125f;
        sc[j] = e; lmax = fmaxf(lmax, e);
    }
    red[tid] = lmax; __syncthreads();
    #pragma unroll
    for (int st = 64; st > 0; st >>= 1) {
        if (tid < st) red[tid] = fmaxf(red[tid], red[tid + st]);
        __syncthreads();
    }
    float m = red[0]; __syncthreads();
    float lsum = 0.f;
    for (int j = tid; j <= qi; j += 128) { float e = __expf(sc[j] - m); sc[j] = e; lsum += e; }
    red[tid] = lsum; __syncthreads();
    #pragma unroll
    for (int st = 64; st > 0; st >>= 1) {
        if (tid < st) red[tid] += red[tid + st];
        __syncthreads();
    }
    float inv = 1.f / red[0]; __syncthreads();
    int end3 = 3 * ((qi & ~127) + 128);
    for (int j = tid; j < end3; j += 128) {
        int kb = j / 192, rr = j - kb * 192;
        int k = kb * 64 + (rr & 63);
        float p = (k <= qi) ? sc[k] * inv : 0.f;
        __nv_bfloat16 o;
        if ((rr >> 6) == 1) {
            __nv_bfloat16 hi = __float2bfloat16(p);
            o = __float2bfloat16(p - __bfloat162float(hi));
        } else o = __float2bfloat16(p);
        prow[j] = o;
    }
}

// ---------------- host ----------------
#define SMEMN(BN) (3 * (128 * 64 * 2 + 64 * (BN) * 2))

extern "C" void kernel_launch(void* const* d_in, const int* in_sizes, int n_in,
                              void* d_out, int out_size)
{
    const int*   idx     = (const int*)  d_in[0];
    const float* tok_emb = (const float*)d_in[1];
    const float* pos_emb = (const float*)d_in[2];
    const float* wq      = (const float*)d_in[3];
    const float* wk      = (const float*)d_in[4];
    const float* wv      = (const float*)d_in[5];
    const float* wproj   = (const float*)d_in[6];
    const float* bproj   = (const float*)d_in[7];
    const float* ln1_g   = (const float*)d_in[8];
    const float* ln1_b   = (const float*)d_in[9];
    const float* ln2_g   = (const float*)d_in[10];
    const float* ln2_b   = (const float*)d_in[11];
    const float* wfc     = (const float*)d_in[12];
    const float* bfc     = (const float*)d_in[13];
    const float* wpr2    = (const float*)d_in[14];
    const float* bpr2    = (const float*)d_in[15];
    const float* lnf_g   = (const float*)d_in[16];
    const float* lnf_b   = (const float*)d_in[17];
    const float* lm_w    = (const float*)d_in[18];
    const float* lm_b    = (const float*)d_in[19];
    float* out = (float*)d_out;

    cudaFuncSetAttribute(hgemm<128, false>, cudaFuncAttributeMaxDynamicSharedMemorySize, SMEMN(128));
    cudaFuncSetAttribute(hgemm<128, true>,  cudaFuncAttributeMaxDynamicSharedMemorySize, SMEMN(128));
    cudaFuncSetAttribute(hgemm<64,  true>,  cudaFuncAttributeMaxDynamicSharedMemorySize, SMEMN(64));

    float *x, *qkv, *S;
    __nv_bfloat16 *xn3, *q3, *k3t, *v3, *P3, *att3, *h3, *w3, *lm3;
    cudaGetSymbolAddress((void**)&x, g_x);     cudaGetSymbolAddress((void**)&xn3, g_xn3);
    cudaGetSymbolAddress((void**)&qkv, g_qkv); cudaGetSymbolAddress((void**)&q3, g_q3);
    cudaGetSymbolAddress((void**)&k3t, g_k3t); cudaGetSymbolAddress((void**)&v3, g_v3);
    cudaGetSymbolAddress((void**)&S, g_S);     cudaGetSymbolAddress((void**)&P3, g_P3);
    cudaGetSymbolAddress((void**)&att3, g_att3); cudaGetSymbolAddress((void**)&h3, g_h3);
    cudaGetSymbolAddress((void**)&w3, g_w3);   cudaGetSymbolAddress((void**)&lm3, g_lm3);

    dim3 tb(32, 8);
    embed_kernel<<<ROWS, 256>>>(idx, tok_emb, pos_emb, x);

    for (int l = 0; l < L; l++) {
        const float* wq_l  = wq  + (size_t)l * E * E;
        const float* wk_l  = wk  + (size_t)l * E * E;
        const float* wv_l  = wv  + (size_t)l * E * E;
        const float* wp_l  = wproj + (size_t)l * E * E;
        const float* wfc_l = wfc + (size_t)l * E * F4;
        const float* wp2_l = wpr2 + (size_t)l * F4 * E;

        layernorm_kernel<<<ROWS, 256>>>(x, ln1_g + l * E, ln1_b + l * E, xn3);

        wsplit3_kernel<<<dim3(E * E / 256, 3), 256>>>(wq_l, wk_l, wv_l, w3);
        hgemm<128, false><<<dim3(16, 18, 1), 128, SMEMN(128)>>>(
            xn3, w3, nullptr, nullptr, qkv, nullptr, 3 * E, 3 * E, 3 * E, 3 * E, 0, 0);

        qpack_kernel<<<ROWS * E / 256, 256>>>(qkv, q3);
        kpackT_kernel<<<dim3(32, 2, BH), tb>>>(qkv, k3t);
        vpack_kernel<<<dim3(T / 4, BH), dim3(64, 4)>>>(qkv, v3);

        hgemm<128, false><<<dim3(8, 8, BH), 128, SMEMN(128)>>>(
            q3, k3t, nullptr, nullptr, S, nullptr, 3 * E, T, T, 192, 2, 0);
        softmax_kernel<<<BH * T, 128>>>(S, P3);
        hgemm<64, true><<<dim3(8, 1, BH), 128, SMEMN(64)>>>(
            P3, v3, nullptr, nullptr, nullptr, att3, 3 * T, HS, 3 * E, 3 * T, 3, 0);

        wsplit_kernel<<<E * E / 256, 256>>>(wp_l, w3, E, E, 0);
        hgemm<128, false><<<dim3(16, 6, 1), 128, SMEMN(128)>>>(
            att3, w3, bproj + l * E, x, x, nullptr, 3 * E, E, E, 3 * E, 0, 0);

        layernorm_kernel<<<ROWS, 256>>>(x, ln2_g + l * E, ln2_b + l * E, xn3);
        wsplit_kernel<<<E * F4 / 256, 256>>>(wfc_l, w3, F4, F4, 0);
        hgemm<128, true><<<dim3(16, 24, 1), 128, SMEMN(128)>>>(
            xn3, w3, bfc + (size_t)l * F4, nullptr, nullptr, h3, 3 * E, F4, 3 * F4, 3 * E, 0, 1);
        wsplit_kernel<<<F4 * E / 256, 256>>>(wp2_l, w3, E, E, 0);
        hgemm<128, false><<<dim3(16, 6, 1), 128, SMEMN(128)>>>(
            h3, w3, bpr2 + l * E, x, x, nullptr, 3 * F4, E, E, 3 * F4, 0, 0);
    }

    layernorm_kernel<<<ROWS, 256>>>(x, lnf_g, lnf_b, xn3);
    wsplit_kernel<<<E * VOCAB / 256, 256>>>(lm_w, lm3, VOCAB, VOCAB, 0);
    hgemm<128, false><<<dim3(16, VOCAB / 128, 1), 128, SMEMN(128)>>>(
        xn3, lm3, lm_b, nullptr, out, nullptr, 3 * E, VOCAB, VOCAB, 3 * E, 0, 0);
}

// round 7
// speedup vs baseline: 1.6272x; 1.1099x over previous
#include <cuda_runtime.h>
#include <cuda_bf16.h>
#include <math.h>

#define BATCH 2
#define T 1024
#define VOCAB 50304
#define E 768
#define L 12
#define H 12
#define HS 64
#define F4 3072
#define ROWS (BATCH * T)
#define BH (BATCH * H)

// ---------------- scratch ----------------
__device__ __align__(128) float          g_x   [ROWS * E];
__device__ __align__(128) __nv_bfloat16  g_xn3 [ROWS * 3 * E];
__device__ __align__(128) float          g_qkv [ROWS * 3 * E];
__device__ __align__(128) __nv_bfloat16  g_att3[ROWS * 3 * E];
__device__ __align__(128) __nv_bfloat16  g_h3  [ROWS * 3 * F4];
__device__ __align__(128) __nv_bfloat16  g_w3  [3 * E * F4];
__device__ __align__(128) __nv_bfloat16  g_lm3 [(size_t)3 * E * VOCAB];

__device__ __forceinline__ unsigned smem_u32(const void* p) {
    unsigned a;
    asm("{ .reg .u64 t; cvta.to.shared.u64 t, %1; cvt.u32.u64 %0, t; }" : "=r"(a) : "l"(p));
    return a;
}
__device__ __forceinline__ void bsplit(float v, __nv_bfloat16& hi, __nv_bfloat16& lo) {
    hi = __float2bfloat16(v);
    lo = __float2bfloat16(v - __bfloat162float(hi));
}
__device__ __forceinline__ unsigned pack2(float a, float b) {
    __nv_bfloat162 p = __floats2bfloat162_rn(a, b);
    return *(unsigned*)&p;
}

#define MMA(acc, a0, a1, a2, a3, b0, b1) \
    asm volatile( \
        "mma.sync.aligned.m16n8k16.row.col.f32.bf16.bf16.f32 " \
        "{%0,%1,%2,%3}, {%4,%5,%6,%7}, {%8,%9}, {%0,%1,%2,%3};" \
        : "+f"((acc)[0]), "+f"((acc)[1]), "+f"((acc)[2]), "+f"((acc)[3]) \
        : "r"(a0), "r"(a1), "r"(a2), "r"(a3), "r"(b0), "r"(b1))

// ---------------- bf16 mma.sync GEMM (plain only) ----------------
// C[M,N] = A[M,K3] @ B[K3,N]; K3 = 3K interleaved-64 bf16x3 split.
template<int BN, bool TOUT>
__global__ void __launch_bounds__(128, 2)
hgemm(const __nv_bfloat16* __restrict__ A, const __nv_bfloat16* __restrict__ Bm,
      const float* __restrict__ bias, const float* __restrict__ res,
      float* __restrict__ Cf, __nv_bfloat16* __restrict__ C3,
      int lda, int ldb, int ldc, int K3, int relu)
{
    constexpr int CHB   = BN / 8;
    constexpr int CNTB  = (64 * CHB) / 128;
    constexpr int ASTG  = 128 * 64 * 2;
    constexpr int BSTG  = 64 * BN * 2;
    constexpr int WARPN = BN / 2;
    constexpr int NF    = WARPN / 8;

    const int m0 = blockIdx.x * 128, n0 = blockIdx.y * BN;

    extern __shared__ __nv_bfloat16 sm[];
    const unsigned Asb = smem_u32(sm);
    const unsigned Bsb = Asb + 3 * ASTG;

    const __nv_bfloat16* Ag = A + (size_t)m0 * lda;
    const __nv_bfloat16* Bg = Bm + n0;
    const size_t rowb = m0;
    const int colb = n0;
    const int kt = K3 / 64;

    const int tid = threadIdx.x;
    const int w = tid >> 5, l = tid & 31;
    const int wm = w >> 1, wn = w & 1;

    auto loadStage = [&](int tt, int s) {
        const __nv_bfloat16* ag = Ag + tt * 64;
        #pragma unroll
        for (int i = 0; i < 8; i++) {
            int id = i * 128 + tid;
            int r = id >> 3, c = id & 7;
            unsigned dst = Asb + s * ASTG + r * 128 + ((c ^ (r & 7)) << 4);
            const __nv_bfloat16* src = ag + (size_t)r * lda + c * 8;
            asm volatile("cp.async.cg.shared.global [%0], [%1], 16;" :: "r"(dst), "l"(src));
        }
        const __nv_bfloat16* bg = Bg + (size_t)tt * 64 * ldb;
        #pragma unroll
        for (int i = 0; i < CNTB; i++) {
            int id = i * 128 + tid;
            int r = id / CHB, c = id % CHB;
            unsigned dst = Bsb + s * BSTG + r * (BN * 2) + (((c & ~7) | ((c ^ (r & 7)) & 7)) << 4);
            const __nv_bfloat16* src = bg + (size_t)r * ldb + c * 8;
            asm volatile("cp.async.cg.shared.global [%0], [%1], 16;" :: "r"(dst), "l"(src));
        }
    };

    if (0 < kt) loadStage(0, 0);
    asm volatile("cp.async.commit_group;");
    if (1 < kt) loadStage(1, 1);
    asm volatile("cp.async.commit_group;");

    float acc[4][NF][4] = {};

    for (int t = 0; t < kt; t++) {
        asm volatile("cp.async.wait_group 1;");
        __syncthreads();
        if (t + 2 < kt) loadStage(t + 2, (t + 2) % 3);
        asm volatile("cp.async.commit_group;");

        const unsigned as = Asb + (t % 3) * ASTG;
        const unsigned bs = Bsb + (t % 3) * BSTG;

        #pragma unroll
        for (int kk = 0; kk < 4; kk++) {
            unsigned fa[4][4], fb[NF][2];
            #pragma unroll
            for (int i = 0; i < 4; i++) {
                int row = wm * 64 + i * 16 + (l & 15);
                int ch  = kk * 2 + (l >> 4);
                unsigned ad = as + row * 128 + ((ch ^ (row & 7)) << 4);
                asm volatile("ldmatrix.sync.aligned.m8n8.x4.shared.b16 {%0,%1,%2,%3}, [%4];"
                    : "=r"(fa[i][0]), "=r"(fa[i][1]), "=r"(fa[i][2]), "=r"(fa[i][3]) : "r"(ad));
            }
            #pragma unroll
            for (int p = 0; p < NF / 2; p++) {
                int row = kk * 16 + (l & 15);
                int ch  = wn * NF + p * 2 + (l >> 4);
                unsigned bd = bs + row * (BN * 2) + (((ch & ~7) | ((ch ^ (row & 7)) & 7)) << 4);
                unsigned r0, r1, r2, r3;
                asm volatile("ldmatrix.sync.aligned.m8n8.x4.trans.shared.b16 {%0,%1,%2,%3}, [%4];"
                    : "=r"(r0), "=r"(r1), "=r"(r2), "=r"(r3) : "r"(bd));
                fb[2*p][0] = r0; fb[2*p][1] = r1; fb[2*p+1][0] = r2; fb[2*p+1][1] = r3;
            }
            #pragma unroll
            for (int i = 0; i < 4; i++)
                #pragma unroll
                for (int j = 0; j < NF; j++)
                    MMA(acc[i][j], fa[i][0], fa[i][1], fa[i][2], fa[i][3], fb[j][0], fb[j][1]);
        }
        __syncthreads();
    }

    #pragma unroll
    for (int i = 0; i < 4; i++) {
        #pragma unroll
        for (int j = 0; j < NF; j++) {
            #pragma unroll
            for (int half = 0; half < 2; half++) {
                int rr = wm * 64 + i * 16 + (l >> 2) + half * 8;
                int c  = wn * WARPN + j * 8 + (l & 3) * 2;
                int cg = colb + c;
                float v0 = acc[i][j][half * 2 + 0];
                float v1 = acc[i][j][half * 2 + 1];
                size_t ro = rowb + rr;
                if (bias) { v0 += bias[cg]; v1 += bias[cg + 1]; }
                if (res)  { v0 += res[ro * ldc + cg]; v1 += res[ro * ldc + cg + 1]; }
                if (relu) { v0 = fmaxf(v0, 0.f); v1 = fmaxf(v1, 0.f); }
                if (TOUT) {
                    int kb = cg >> 6, kr = cg & 63;
                    size_t base = ro * ldc + 192 * kb + kr;
                    __nv_bfloat16 h0, l0, h1, l1;
                    bsplit(v0, h0, l0); bsplit(v1, h1, l1);
                    C3[base]       = h0; C3[base + 1]   = h1;
                    C3[base + 64]  = l0; C3[base + 65]  = l1;
                    C3[base + 128] = h0; C3[base + 129] = h1;
                } else {
                    Cf[ro * ldc + cg]     = v0;
                    Cf[ro * ldc + cg + 1] = v1;
                }
            }
        }
    }
}

// ---------------- fused flash attention ----------------
// grid (16 m-tiles of 64 q-rows, BH). 128 threads, 4 warps x 16 rows.
// Reads qkv fp32, writes att3 (triple A-layout). bf16x3 everywhere.
__global__ void __launch_bounds__(128, 2)
flash_kernel(const float* __restrict__ qkv, __nv_bfloat16* __restrict__ att3)
{
    const int m0 = blockIdx.x * 64;
    const int z = blockIdx.y, b = z / H, h = z - b * H;
    const int tid = threadIdx.x, w = tid >> 5, l = tid & 31;
    const int g = l >> 2, t4 = l & 3;

    extern __shared__ __nv_bfloat16 sm[];
    const unsigned KsA = smem_u32(sm);            // [128 tok][192]
    const unsigned VsA = KsA + 128 * 192 * 2;     // [384 k3][64]

    // ---- Q fragments (A-side bf16x3), scale folded: 0.125*log2(e) ----
    unsigned qhi[4][4], qlo[4][4];
    {
        const float sc = 0.125f * 1.4426950408889634f;
        const float* q0 = qkv + (size_t)(b * T + m0 + w * 16 + g) * (3 * E) + h * 64;
        const float* q1 = q0 + (size_t)8 * (3 * E);
        #pragma unroll
        for (int f = 0; f < 4; f++)
        #pragma unroll
        for (int hv = 0; hv < 2; hv++) {
            int d = f * 16 + hv * 8 + t4 * 2;
            float2 a = *(const float2*)(q0 + d);
            float2 c = *(const float2*)(q1 + d);
            a.x *= sc; a.y *= sc; c.x *= sc; c.y *= sc;
            __nv_bfloat16 ahx, alx, ahy, aly, chx, clx, chy, cly;
            bsplit(a.x, ahx, alx); bsplit(a.y, ahy, aly);
            bsplit(c.x, chx, clx); bsplit(c.y, chy, cly);
            qhi[f][hv * 2 + 0] = pack2(__bfloat162float(ahx), __bfloat162float(ahy));
            qhi[f][hv * 2 + 1] = pack2(__bfloat162float(chx), __bfloat162float(chy));
            qlo[f][hv * 2 + 0] = pack2(__bfloat162float(alx), __bfloat162float(aly));
            qlo[f][hv * 2 + 1] = pack2(__bfloat162float(clx), __bfloat162float(cly));
        }
    }

    float M0 = -1e30f, M1 = -1e30f, L0 = 0.f, L1 = 0.f;
    float O[8][4] = {};

    const int nkt = (m0 + 191) / 128;
    for (int j0 = 0; j0 < nkt; j0++) {
        __syncthreads();
        // ---- load K,V tile (128 tokens) into smem with bf16x3 layout ----
        {
            const float* kg = qkv + (size_t)(b * T + j0 * 128) * (3 * E) + E + h * 64;
            const float* vg = kg + E;
            #pragma unroll
            for (int it = 0; it < 16; it++) {
                int id = it * 128 + tid;
                int tok = id >> 4, dq = (id & 15) * 4;
                float4 v = *(const float4*)(kg + (size_t)tok * (3 * E) + dq);
                __nv_bfloat16 h0,l0,h1,l1,h2,l2,h3,l3;
                bsplit(v.x,h0,l0); bsplit(v.y,h1,l1); bsplit(v.z,h2,l2); bsplit(v.w,h3,l3);
                unsigned hp0 = pack2(__bfloat162float(h0), __bfloat162float(h1));
                unsigned hp1 = pack2(__bfloat162float(h2), __bfloat162float(h3));
                unsigned lp0 = pack2(__bfloat162float(l0), __bfloat162float(l1));
                unsigned lp1 = pack2(__bfloat162float(l2), __bfloat162float(l3));
                unsigned rbase = KsA + tok * 384;
                #pragma unroll
                for (int blk = 0; blk < 3; blk++) {
                    int col = blk * 64 + dq;
                    int c = col >> 3;
                    unsigned ad = rbase + ((c ^ (tok & 7)) << 4) + (col & 7) * 2;
                    *(unsigned*)(unsigned long long)0; // placeholder removed below
                    unsigned v0 = (blk < 2) ? hp0 : lp0;
                    unsigned v1 = (blk < 2) ? hp1 : lp1;
                    asm volatile("st.shared.b32 [%0], %1;" :: "r"(ad), "r"(v0));
                    asm volatile("st.shared.b32 [%0], %1;" :: "r"(ad + 4), "r"(v1));
                }
                // V: rows = k3 (token-major triple), cols = d
                float4 vv = *(const float4*)(vg + (size_t)tok * (3 * E) + dq);
                bsplit(vv.x,h0,l0); bsplit(vv.y,h1,l1); bsplit(vv.z,h2,l2); bsplit(vv.w,h3,l3);
                hp0 = pack2(__bfloat162float(h0), __bfloat162float(h1));
                hp1 = pack2(__bfloat162float(h2), __bfloat162float(h3));
                lp0 = pack2(__bfloat162float(l0), __bfloat162float(l1));
                lp1 = pack2(__bfloat162float(l2), __bfloat162float(l3));
                int tb = tok >> 6, tt = tok & 63;
                int c = dq >> 3;
                #pragma unroll
                for (int blk = 0; blk < 3; blk++) {
                    int row = tb * 192 + blk * 64 + tt;
                    unsigned ad = VsA + row * 128 + ((c ^ (row & 7)) << 4) + (dq & 7) * 2;
                    unsigned v0 = (blk < 2) ? hp0 : lp0;
                    unsigned v1 = (blk < 2) ? hp1 : lp1;
                    asm volatile("st.shared.b32 [%0], %1;" :: "r"(ad), "r"(v0));
                    asm volatile("st.shared.b32 [%0], %1;" :: "r"(ad + 4), "r"(v1));
                }
            }
        }
        __syncthreads();

        // ---- S = Q @ K^T (3-term over k3=192) ----
        float Sa[16][4];
        #pragma unroll
        for (int j = 0; j < 16; j++) { Sa[j][0]=0.f; Sa[j][1]=0.f; Sa[j][2]=0.f; Sa[j][3]=0.f; }

        #pragma unroll
        for (int f = 0; f < 12; f++) {
            const unsigned* A = (f < 4) ? qhi[f] : (f < 8) ? qlo[f - 4] : qhi[f - 8];
            #pragma unroll
            for (int nn = 0; nn < 8; nn++) {
                int row = nn * 16 + ((l >> 4) << 3) + (l & 7);
                int ch  = 2 * f + ((l >> 3) & 1);
                unsigned ad = KsA + row * 384 + (((ch & ~7) | ((ch ^ (row & 7)) & 7)) << 4);
                unsigned r0, r1, r2, r3;
                asm volatile("ldmatrix.sync.aligned.m8n8.x4.shared.b16 {%0,%1,%2,%3}, [%4];"
                    : "=r"(r0), "=r"(r1), "=r"(r2), "=r"(r3) : "r"(ad));
                MMA(Sa[nn*2],   A[0], A[1], A[2], A[3], r0, r1);
                MMA(Sa[nn*2+1], A[0], A[1], A[2], A[3], r2, r3);
            }
        }

        // ---- causal mask (last tile only) ----
        if (j0 == nkt - 1) {
            int r0 = m0 + w * 16 + g, r1 = r0 + 8, cb = j0 * 128 + t4 * 2;
            #pragma unroll
            for (int j = 0; j < 16; j++) {
                int c0 = cb + j * 8, c1 = c0 + 1;
                if (c0 > r0) Sa[j][0] = -1e30f;
                if (c1 > r0) Sa[j][1] = -1e30f;
                if (c0 > r1) Sa[j][2] = -1e30f;
                if (c1 > r1) Sa[j][3] = -1e30f;
            }
        }

        // ---- online softmax (base-2) ----
        float mx0 = -1e30f, mx1 = -1e30f;
        #pragma unroll
        for (int j = 0; j < 16; j++) {
            mx0 = fmaxf(mx0, fmaxf(Sa[j][0], Sa[j][1]));
            mx1 = fmaxf(mx1, fmaxf(Sa[j][2], Sa[j][3]));
        }
        mx0 = fmaxf(mx0, __shfl_xor_sync(~0u, mx0, 1));
        mx0 = fmaxf(mx0, __shfl_xor_sync(~0u, mx0, 2));
        mx1 = fmaxf(mx1, __shfl_xor_sync(~0u, mx1, 1));
        mx1 = fmaxf(mx1, __shfl_xor_sync(~0u, mx1, 2));
        float Mn0 = fmaxf(M0, mx0), Mn1 = fmaxf(M1, mx1);
        float sc0 = exp2f(M0 - Mn0), sc1 = exp2f(M1 - Mn1);
        float ls0 = 0.f, ls1 = 0.f;
        #pragma unroll
        for (int j = 0; j < 16; j++) {
            Sa[j][0] = exp2f(Sa[j][0] - Mn0); ls0 += Sa[j][0];
            Sa[j][1] = exp2f(Sa[j][1] - Mn0); ls0 += Sa[j][1];
            Sa[j][2] = exp2f(Sa[j][2] - Mn1); ls1 += Sa[j][2];
            Sa[j][3] = exp2f(Sa[j][3] - Mn1); ls1 += Sa[j][3];
        }
        ls0 += __shfl_xor_sync(~0u, ls0, 1); ls0 += __shfl_xor_sync(~0u, ls0, 2);
        ls1 += __shfl_xor_sync(~0u, ls1, 1); ls1 += __shfl_xor_sync(~0u, ls1, 2);
        L0 = L0 * sc0 + ls0; L1 = L1 * sc1 + ls1;
        M0 = Mn0; M1 = Mn1;
        #pragma unroll
        for (int nf = 0; nf < 8; nf++) {
            O[nf][0] *= sc0; O[nf][1] *= sc0; O[nf][2] *= sc1; O[nf][3] *= sc1;
        }

        // ---- O += P @ V (3-term, A from accumulator relayout) ----
        #pragma unroll
        for (int tb = 0; tb < 2; tb++) {
            unsigned Ahi[4][4], Alo[4][4];
            #pragma unroll
            for (int f = 0; f < 4; f++) {
                int j = tb * 8 + 2 * f;
                #pragma unroll
                for (int q = 0; q < 2; q++) {       // q=0: Sa[j], q=1: Sa[j+1] (k+8)
                    float p0 = Sa[j+q][0], p1 = Sa[j+q][1], p2 = Sa[j+q][2], p3 = Sa[j+q][3];
                    __nv_bfloat16 h0,l0,h1,l1,h2,l2,h3,l3;
                    bsplit(p0,h0,l0); bsplit(p1,h1,l1); bsplit(p2,h2,l2); bsplit(p3,h3,l3);
                    Ahi[f][q*2+0] = pack2(__bfloat162float(h0), __bfloat162float(h1));
                    Ahi[f][q*2+1] = pack2(__bfloat162float(h2), __bfloat162float(h3));
                    Alo[f][q*2+0] = pack2(__bfloat162float(l0), __bfloat162float(l1));
                    Alo[f][q*2+1] = pack2(__bfloat162float(l2), __bfloat162float(l3));
                }
            }
            #pragma unroll
            for (int sub = 0; sub < 3; sub++) {
                #pragma unroll
                for (int f = 0; f < 4; f++) {
                    const unsigned* A = (sub == 1) ? Alo[f] : Ahi[f];
                    int kb16 = tb * 12 + sub * 4 + f;
                    #pragma unroll
                    for (int nn = 0; nn < 4; nn++) {
                        int row = kb16 * 16 + (l & 15);
                        int ch  = nn * 2 + (l >> 4);
                        unsigned ad = VsA + row * 128 + ((ch ^ (row & 7)) << 4);
                        unsigned r0, r1, r2, r3;
                        asm volatile("ldmatrix.sync.aligned.m8n8.x4.trans.shared.b16 {%0,%1,%2,%3}, [%4];"
                            : "=r"(r0), "=r"(r1), "=r"(r2), "=r"(r3) : "r"(ad));
                        MMA(O[nn*2],   A[0], A[1], A[2], A[3], r0, r1);
                        MMA(O[nn*2+1], A[0], A[1], A[2], A[3], r2, r3);
                    }
                }
            }
        }
    }

    // ---- epilogue: att3 triple layout ----
    float i0 = 1.f / L0, i1 = 1.f / L1;
    size_t r0 = (size_t)(b * T + m0 + w * 16 + g) * (3 * E) + 192 * h;
    size_t r1 = r0 + (size_t)8 * (3 * E);
    #pragma unroll
    for (int nf = 0; nf < 8; nf++) {
        #pragma unroll
        for (int e = 0; e < 2; e++) {
            int d = nf * 8 + t4 * 2 + e;
            __nv_bfloat16 hi, lo;
            bsplit(O[nf][e] * i0, hi, lo);
            att3[r0 + d] = hi; att3[r0 + 64 + d] = lo; att3[r0 + 128 + d] = hi;
            bsplit(O[nf][2 + e] * i1, hi, lo);
            att3[r1 + d] = hi; att3[r1 + 64 + d] = lo; att3[r1 + 128 + d] = hi;
        }
    }
}

// ---------------- small kernels ----------------
__global__ void embed_kernel(const int* __restrict__ idx, const float* __restrict__ te,
                             const float* __restrict__ pe, float* __restrict__ x)
{
    int row = blockIdx.x, t = row % T, tok = idx[row];
    const float* a = te + (size_t)tok * E;
    const float* b = pe + (size_t)t * E;
    float* xr = x + (size_t)row * E;
    for (int i = threadIdx.x; i < E; i += blockDim.x) xr[i] = a[i] + b[i];
}

__global__ __launch_bounds__(256)
void layernorm_kernel(const float* __restrict__ x, const float* __restrict__ g,
                      const float* __restrict__ b, __nv_bfloat16* __restrict__ y3)
{
    int row = blockIdx.x, tid = threadIdx.x;
    const float* xr = x + (size_t)row * E;
    float s = 0.f, s2 = 0.f;
    for (int i = tid; i < E; i += 256) { float v = xr[i]; s += v; s2 += v * v; }
    #pragma unroll
    for (int o = 16; o > 0; o >>= 1) {
        s += __shfl_down_sync(~0u, s, o); s2 += __shfl_down_sync(~0u, s2, o);
    }
    __shared__ float ws[8], ws2[8];
    if ((tid & 31) == 0) { ws[tid >> 5] = s; ws2[tid >> 5] = s2; }
    __syncthreads();
    if (tid == 0) {
        float a = 0.f, a2 = 0.f;
        #pragma unroll
        for (int i = 0; i < 8; i++) { a += ws[i]; a2 += ws2[i]; }
        ws[0] = a; ws2[0] = a2;
    }
    __syncthreads();
    float mean = ws[0] / E, var = ws2[0] / E - mean * mean;
    float inv = rsqrtf(var + 1e-5f);
    for (int i = tid; i < E; i += 256) {
        float v = (xr[i] - mean) * inv * g[i] + b[i];
        __nv_bfloat16 hi, lo; bsplit(v, hi, lo);
        size_t base = (size_t)row * (3 * E) + 192 * (i >> 6) + (i & 63);
        y3[base] = hi; y3[base + 64] = lo; y3[base + 128] = hi;
    }
}

__global__ void wsplit_kernel(const float* __restrict__ src, __nv_bfloat16* __restrict__ dst,
                              int N, int dstLD, int colOff)
{
    size_t i = (size_t)blockIdx.x * 256 + threadIdx.x;
    int n = (int)(i % N), k = (int)(i / N);
    float v = src[i];
    __nv_bfloat16 hi, lo; bsplit(v, hi, lo);
    size_t rb = (size_t)(192 * (k >> 6) + (k & 63)) * dstLD + colOff + n;
    dst[rb] = hi; dst[rb + (size_t)64 * dstLD] = hi; dst[rb + (size_t)128 * dstLD] = lo;
}

__global__ void wsplit3_kernel(const float* __restrict__ s0, const float* __restrict__ s1,
                               const float* __restrict__ s2, __nv_bfloat16* __restrict__ dst)
{
    int z = blockIdx.y;
    const float* src = (z == 0) ? s0 : (z == 1) ? s1 : s2;
    size_t i = (size_t)blockIdx.x * 256 + threadIdx.x;
    int n = (int)(i % E), k = (int)(i / E);
    float v = src[i];
    __nv_bfloat16 hi, lo; bsplit(v, hi, lo);
    size_t rb = (size_t)(192 * (k >> 6) + (k & 63)) * (3 * E) + z * E + n;
    dst[rb] = hi; dst[rb + (size_t)64 * 3 * E] = hi; dst[rb + (size_t)128 * 3 * E] = lo;
}

// ---------------- host ----------------
#define SMEMN(BN) (3 * (128 * 64 * 2 + 64 * (BN) * 2))
#define SMEMFL (128 * 192 * 2 + 384 * 64 * 2)

extern "C" void kernel_launch(void* const* d_in, const int* in_sizes, int n_in,
                              void* d_out, int out_size)
{
    const int*   idx     = (const int*)  d_in[0];
    const float* tok_emb = (const float*)d_in[1];
    const float* pos_emb = (const float*)d_in[2];
    const float* wq      = (const float*)d_in[3];
    const float* wk      = (const float*)d_in[4];
    const float* wv      = (const float*)d_in[5];
    const float* wproj   = (const float*)d_in[6];
    const float* bproj   = (const float*)d_in[7];
    const float* ln1_g   = (const float*)d_in[8];
    const float* ln1_b   = (const float*)d_in[9];
    const float* ln2_g   = (const float*)d_in[10];
    const float* ln2_b   = (const float*)d_in[11];
    const float* wfc     = (const float*)d_in[12];
    const float* bfc     = (const float*)d_in[13];
    const float* wpr2    = (const float*)d_in[14];
    const float* bpr2    = (const float*)d_in[15];
    const float* lnf_g   = (const float*)d_in[16];
    const float* lnf_b   = (const float*)d_in[17];
    const float* lm_w    = (const float*)d_in[18];
    const float* lm_b    = (const float*)d_in[19];
    float* out = (float*)d_out;

    cudaFuncSetAttribute(hgemm<128, false>, cudaFuncAttributeMaxDynamicSharedMemorySize, SMEMN(128));
    cudaFuncSetAttribute(hgemm<128, true>,  cudaFuncAttributeMaxDynamicSharedMemorySize, SMEMN(128));
    cudaFuncSetAttribute(flash_kernel, cudaFuncAttributeMaxDynamicSharedMemorySize, SMEMFL);

    float *x, *qkv;
    __nv_bfloat16 *xn3, *att3, *h3, *w3, *lm3;
    cudaGetSymbolAddress((void**)&x, g_x);     cudaGetSymbolAddress((void**)&xn3, g_xn3);
    cudaGetSymbolAddress((void**)&qkv, g_qkv); cudaGetSymbolAddress((void**)&att3, g_att3);
    cudaGetSymbolAddress((void**)&h3, g_h3);   cudaGetSymbolAddress((void**)&w3, g_w3);
    cudaGetSymbolAddress((void**)&lm3, g_lm3);

    embed_kernel<<<ROWS, 256>>>(idx, tok_emb, pos_emb, x);

    for (int l = 0; l < L; l++) {
        const float* wq_l  = wq  + (size_t)l * E * E;
        const float* wk_l  = wk  + (size_t)l * E * E;
        const float* wv_l  = wv  + (size_t)l * E * E;
        const float* wp_l  = wproj + (size_t)l * E * E;
        const float* wfc_l = wfc + (size_t)l * E * F4;
        const float* wp2_l = wpr2 + (size_t)l * F4 * E;

        layernorm_kernel<<<ROWS, 256>>>(x, ln1_g + l * E, ln1_b + l * E, xn3);

        wsplit3_kernel<<<dim3(E * E / 256, 3), 256>>>(wq_l, wk_l, wv_l, w3);
        hgemm<128, false><<<dim3(16, 18), 128, SMEMN(128)>>>(
            xn3, w3, nullptr, nullptr, qkv, nullptr, 3 * E, 3 * E, 3 * E, 3 * E, 0);

        flash_kernel<<<dim3(16, BH), 128, SMEMFL>>>(qkv, att3);

        wsplit_kernel<<<E * E / 256, 256>>>(wp_l, w3, E, E, 0);
        hgemm<128, false><<<dim3(16, 6), 128, SMEMN(128)>>>(
            att3, w3, bproj + l * E, x, x, nullptr, 3 * E, E, E, 3 * E, 0);

        layernorm_kernel<<<ROWS, 256>>>(x, ln2_g + l * E, ln2_b + l * E, xn3);
        wsplit_kernel<<<E * F4 / 256, 256>>>(wfc_l, w3, F4, F4, 0);
        hgemm<128, true><<<dim3(16, 24), 128, SMEMN(128)>>>(
            xn3, w3, bfc + (size_t)l * F4, nullptr, nullptr, h3, 3 * E, F4, 3 * F4, 3 * E, 1);
        wsplit_kernel<<<F4 * E / 256, 256>>>(wp2_l, w3, E, E, 0);
        hgemm<128, false><<<dim3(16, 6), 128, SMEMN(128)>>>(
            h3, w3, bpr2 + l * E, x, x, nullptr, 3 * F4, E, E, 3 * F4, 0);
    }

    layernorm_kernel<<<ROWS, 256>>>(x, lnf_g, lnf_b, xn3);
    wsplit_kernel<<<E * VOCAB / 256, 256>>>(lm_w, lm3, VOCAB, VOCAB, 0);
    hgemm<128, false><<<dim3(16, VOCAB / 128), 128, SMEMN(128)>>>(
        xn3, lm3, lm_b, nullptr, out, nullptr, 3 * E, VOCAB, VOCAB, 3 * E, 0);
}

// round 10
// speedup vs baseline: 1.6360x; 1.0054x over previous
#include <cuda_runtime.h>
#include <cuda_bf16.h>
#include <math.h>

#define BATCH 2
#define T 1024
#define VOCAB 50304
#define E 768
#define L 12
#define H 12
#define HS 64
#define F4 3072
#define ROWS (BATCH * T)
#define BH (BATCH * H)

// ---------------- scratch ----------------
__device__ __align__(128) float          g_x   [ROWS * E];
__device__ __align__(128) __nv_bfloat16  g_xn3 [ROWS * 3 * E];
__device__ __align__(128) float          g_qkv [ROWS * 3 * E];
__device__ __align__(128) __nv_bfloat16  g_att3[ROWS * 3 * E];
__device__ __align__(128) __nv_bfloat16  g_h3  [ROWS * 3 * F4];
__device__ __align__(128) __nv_bfloat16  g_w3  [3 * E * F4];
__device__ __align__(128) __nv_bfloat16  g_lm3 [(size_t)3 * E * VOCAB];

__device__ __forceinline__ unsigned smem_u32(const void* p) {
    unsigned a;
    asm("{ .reg .u64 t; cvta.to.shared.u64 t, %1; cvt.u32.u64 %0, t; }" : "=r"(a) : "l"(p));
    return a;
}
__device__ __forceinline__ void bsplit(float v, __nv_bfloat16& hi, __nv_bfloat16& lo) {
    hi = __float2bfloat16(v);
    lo = __float2bfloat16(v - __bfloat162float(hi));
}
__device__ __forceinline__ unsigned pack2(float a, float b) {
    __nv_bfloat162 p = __floats2bfloat162_rn(a, b);
    return *(unsigned*)&p;
}

#define MMA(acc, a0, a1, a2, a3, b0, b1) \
    asm volatile( \
        "mma.sync.aligned.m16n8k16.row.col.f32.bf16.bf16.f32 " \
        "{%0,%1,%2,%3}, {%4,%5,%6,%7}, {%8,%9}, {%0,%1,%2,%3};" \
        : "+f"((acc)[0]), "+f"((acc)[1]), "+f"((acc)[2]), "+f"((acc)[3]) \
        : "r"(a0), "r"(a1), "r"(a2), "r"(a3), "r"(b0), "r"(b1))

// ---------------- bf16 mma.sync GEMM v4 ----------------
// BM=64, BN=128, 128 threads (4 warps, 2x2), warp tile 32x64. 3-stage cp.async.
// 3 CTAs/SM resident. C[M,N] = A[M,K3] @ B[K3,N]; K3 = 3K interleaved-64 bf16x3.
template<int BN, bool TOUT>
__global__ void __launch_bounds__(128, 3)
hgemm(const __nv_bfloat16* __restrict__ A, const __nv_bfloat16* __restrict__ Bm,
      const float* __restrict__ bias, const float* __restrict__ res,
      float* __restrict__ Cf, __nv_bfloat16* __restrict__ C3,
      int lda, int ldb, int ldc, int K3, int relu)
{
    constexpr int CHB   = BN / 8;
    constexpr int CNTB  = (64 * CHB) / 128;
    constexpr int ASTG  = 64 * 64 * 2;        // bytes per A stage (64 rows x 128B)
    constexpr int BSTG  = 64 * BN * 2;
    constexpr int WARPN = BN / 2;
    constexpr int NF    = WARPN / 8;

    const int m0 = blockIdx.x * 64, n0 = blockIdx.y * BN;

    extern __shared__ __nv_bfloat16 sm[];
    const unsigned Asb = smem_u32(sm);
    const unsigned Bsb = Asb + 3 * ASTG;

    const __nv_bfloat16* Ag = A + (size_t)m0 * lda;
    const __nv_bfloat16* Bg = Bm + n0;
    const size_t rowb = m0;
    const int colb = n0;
    const int kt = K3 / 64;

    const int tid = threadIdx.x;
    const int w = tid >> 5, l = tid & 31;
    const int wm = w >> 1, wn = w & 1;

    auto loadStage = [&](int tt, int s) {
        const __nv_bfloat16* ag = Ag + tt * 64;
        #pragma unroll
        for (int i = 0; i < 4; i++) {
            int id = i * 128 + tid;
            int r = id >> 3, c = id & 7;
            unsigned dst = Asb + s * ASTG + r * 128 + ((c ^ (r & 7)) << 4);
            const __nv_bfloat16* src = ag + (size_t)r * lda + c * 8;
            asm volatile("cp.async.cg.shared.global [%0], [%1], 16;" :: "r"(dst), "l"(src));
        }
        const __nv_bfloat16* bg = Bg + (size_t)tt * 64 * ldb;
        #pragma unroll
        for (int i = 0; i < CNTB; i++) {
            int id = i * 128 + tid;
            int r = id / CHB, c = id % CHB;
            unsigned dst = Bsb + s * BSTG + r * (BN * 2) + (((c & ~7) | ((c ^ (r & 7)) & 7)) << 4);
            const __nv_bfloat16* src = bg + (size_t)r * ldb + c * 8;
            asm volatile("cp.async.cg.shared.global [%0], [%1], 16;" :: "r"(dst), "l"(src));
        }
    };

    if (0 < kt) loadStage(0, 0);
    asm volatile("cp.async.commit_group;");
    if (1 < kt) loadStage(1, 1);
    asm volatile("cp.async.commit_group;");

    float acc[2][NF][4] = {};

    for (int t = 0; t < kt; t++) {
        asm volatile("cp.async.wait_group 1;");
        __syncthreads();
        if (t + 2 < kt) loadStage(t + 2, (t + 2) % 3);
        asm volatile("cp.async.commit_group;");

        const unsigned as = Asb + (t % 3) * ASTG;
        const unsigned bs = Bsb + (t % 3) * BSTG;

        #pragma unroll
        for (int kk = 0; kk < 4; kk++) {
            unsigned fa[2][4], fb[NF][2];
            #pragma unroll
            for (int i = 0; i < 2; i++) {
                int row = wm * 32 + i * 16 + (l & 15);
                int ch  = kk * 2 + (l >> 4);
                unsigned ad = as + row * 128 + ((ch ^ (row & 7)) << 4);
                asm volatile("ldmatrix.sync.aligned.m8n8.x4.shared.b16 {%0,%1,%2,%3}, [%4];"
                    : "=r"(fa[i][0]), "=r"(fa[i][1]), "=r"(fa[i][2]), "=r"(fa[i][3]) : "r"(ad));
            }
            #pragma unroll
            for (int p = 0; p < NF / 2; p++) {
                int row = kk * 16 + (l & 15);
                int ch  = wn * NF + p * 2 + (l >> 4);
                unsigned bd = bs + row * (BN * 2) + (((ch & ~7) | ((ch ^ (row & 7)) & 7)) << 4);
                unsigned r0, r1, r2, r3;
                asm volatile("ldmatrix.sync.aligned.m8n8.x4.trans.shared.b16 {%0,%1,%2,%3}, [%4];"
                    : "=r"(r0), "=r"(r1), "=r"(r2), "=r"(r3) : "r"(bd));
                fb[2*p][0] = r0; fb[2*p][1] = r1; fb[2*p+1][0] = r2; fb[2*p+1][1] = r3;
            }
            #pragma unroll
            for (int i = 0; i < 2; i++)
                #pragma unroll
                for (int j = 0; j < NF; j++)
                    MMA(acc[i][j], fa[i][0], fa[i][1], fa[i][2], fa[i][3], fb[j][0], fb[j][1]);
        }
        __syncthreads();
    }

    #pragma unroll
    for (int i = 0; i < 2; i++) {
        #pragma unroll
        for (int j = 0; j < NF; j++) {
            #pragma unroll
            for (int half = 0; half < 2; half++) {
                int rr = wm * 32 + i * 16 + (l >> 2) + half * 8;
                int c  = wn * WARPN + j * 8 + (l & 3) * 2;
                int cg = colb + c;
                float v0 = acc[i][j][half * 2 + 0];
                float v1 = acc[i][j][half * 2 + 1];
                size_t ro = rowb + rr;
                if (bias) { v0 += bias[cg]; v1 += bias[cg + 1]; }
                if (res)  { v0 += res[ro * ldc + cg]; v1 += res[ro * ldc + cg + 1]; }
                if (relu) { v0 = fmaxf(v0, 0.f); v1 = fmaxf(v1, 0.f); }
                if (TOUT) {
                    int kb = cg >> 6, kr = cg & 63;
                    size_t base = ro * ldc + 192 * kb + kr;
                    __nv_bfloat16 h0, l0, h1, l1;
                    bsplit(v0, h0, l0); bsplit(v1, h1, l1);
                    C3[base]       = h0; C3[base + 1]   = h1;
                    C3[base + 64]  = l0; C3[base + 65]  = l1;
                    C3[base + 128] = h0; C3[base + 129] = h1;
                } else {
                    Cf[ro * ldc + cg]     = v0;
                    Cf[ro * ldc + cg + 1] = v1;
                }
            }
        }
    }
}

// ---------------- fused flash attention ----------------
__global__ void __launch_bounds__(128, 2)
flash_kernel(const float* __restrict__ qkv, __nv_bfloat16* __restrict__ att3)
{
    const int m0 = blockIdx.x * 64;
    const int z = blockIdx.y, b = z / H, h = z - b * H;
    const int tid = threadIdx.x, w = tid >> 5, l = tid & 31;
    const int g = l >> 2, t4 = l & 3;

    extern __shared__ __nv_bfloat16 sm[];
    const unsigned KsA = smem_u32(sm);            // [128 tok][192]
    const unsigned VsA = KsA + 128 * 192 * 2;     // [384 k3][64]

    unsigned qhi[4][4], qlo[4][4];
    {
        const float sc = 0.125f * 1.4426950408889634f;
        const float* q0 = qkv + (size_t)(b * T + m0 + w * 16 + g) * (3 * E) + h * 64;
        const float* q1 = q0 + (size_t)8 * (3 * E);
        #pragma unroll
        for (int f = 0; f < 4; f++)
        #pragma unroll
        for (int hv = 0; hv < 2; hv++) {
            int d = f * 16 + hv * 8 + t4 * 2;
            float2 a = *(const float2*)(q0 + d);
            float2 c = *(const float2*)(q1 + d);
            a.x *= sc; a.y *= sc; c.x *= sc; c.y *= sc;
            __nv_bfloat16 ahx, alx, ahy, aly, chx, clx, chy, cly;
            bsplit(a.x, ahx, alx); bsplit(a.y, ahy, aly);
            bsplit(c.x, chx, clx); bsplit(c.y, chy, cly);
            qhi[f][hv * 2 + 0] = pack2(__bfloat162float(ahx), __bfloat162float(ahy));
            qhi[f][hv * 2 + 1] = pack2(__bfloat162float(chx), __bfloat162float(chy));
            qlo[f][hv * 2 + 0] = pack2(__bfloat162float(alx), __bfloat162float(aly));
            qlo[f][hv * 2 + 1] = pack2(__bfloat162float(clx), __bfloat162float(cly));
        }
    }

    float M0 = -1e30f, M1 = -1e30f, L0 = 0.f, L1 = 0.f;
    float O[8][4] = {};

    const int nkt = (m0 + 191) / 128;
    for (int j0 = 0; j0 < nkt; j0++) {
        __syncthreads();
        {
            const float* kg = qkv + (size_t)(b * T + j0 * 128) * (3 * E) + E + h * 64;
            const float* vg = kg + E;
            #pragma unroll
            for (int it = 0; it < 16; it++) {
                int id = it * 128 + tid;
                int tok = id >> 4, dq = (id & 15) * 4;
                float4 v = *(const float4*)(kg + (size_t)tok * (3 * E) + dq);
                __nv_bfloat16 h0,l0,h1,l1,h2,l2,h3,l3;
                bsplit(v.x,h0,l0); bsplit(v.y,h1,l1); bsplit(v.z,h2,l2); bsplit(v.w,h3,l3);
                unsigned hp0 = pack2(__bfloat162float(h0), __bfloat162float(h1));
                unsigned hp1 = pack2(__bfloat162float(h2), __bfloat162float(h3));
                unsigned lp0 = pack2(__bfloat162float(l0), __bfloat162float(l1));
                unsigned lp1 = pack2(__bfloat162float(l2), __bfloat162float(l3));
                unsigned rbase = KsA + tok * 384;
                #pragma unroll
                for (int blk = 0; blk < 3; blk++) {
                    int col = blk * 64 + dq;
                    int c = col >> 3;
                    unsigned ad = rbase + (((c & ~7) | ((c ^ (tok & 7)) & 7)) << 4) + (col & 7) * 2;
                    unsigned v0 = (blk < 2) ? hp0 : lp0;
                    unsigned v1 = (blk < 2) ? hp1 : lp1;
                    asm volatile("st.shared.b32 [%0], %1;" :: "r"(ad), "r"(v0));
                    asm volatile("st.shared.b32 [%0], %1;" :: "r"(ad + 4), "r"(v1));
                }
                float4 vv = *(const float4*)(vg + (size_t)tok * (3 * E) + dq);
                bsplit(vv.x,h0,l0); bsplit(vv.y,h1,l1); bsplit(vv.z,h2,l2); bsplit(vv.w,h3,l3);
                hp0 = pack2(__bfloat162float(h0), __bfloat162float(h1));
                hp1 = pack2(__bfloat162float(h2), __bfloat162float(h3));
                lp0 = pack2(__bfloat162float(l0), __bfloat162float(l1));
                lp1 = pack2(__bfloat162float(l2), __bfloat162float(l3));
                int tb = tok >> 6, tt = tok & 63;
                int c = dq >> 3;
                #pragma unroll
                for (int blk = 0; blk < 3; blk++) {
                    int row = tb * 192 + blk * 64 + tt;
                    unsigned ad = VsA + row * 128 + ((c ^ (row & 7)) << 4) + (dq & 7) * 2;
                    unsigned v0 = (blk < 2) ? hp0 : lp0;
                    unsigned v1 = (blk < 2) ? hp1 : lp1;
                    asm volatile("st.shared.b32 [%0], %1;" :: "r"(ad), "r"(v0));
                    asm volatile("st.shared.b32 [%0], %1;" :: "r"(ad + 4), "r"(v1));
                }
            }
        }
        __syncthreads();

        float Sa[16][4];
        #pragma unroll
        for (int j = 0; j < 16; j++) { Sa[j][0]=0.f; Sa[j][1]=0.f; Sa[j][2]=0.f; Sa[j][3]=0.f; }

        #pragma unroll
        for (int f = 0; f < 12; f++) {
            const unsigned* A = (f < 4) ? qhi[f] : (f < 8) ? qlo[f - 4] : qhi[f - 8];
            #pragma unroll
            for (int nn = 0; nn < 8; nn++) {
                int row = nn * 16 + ((l >> 4) << 3) + (l & 7);
                int ch  = 2 * f + ((l >> 3) & 1);
                unsigned ad = KsA + row * 384 + (((ch & ~7) | ((ch ^ (row & 7)) & 7)) << 4);
                unsigned r0, r1, r2, r3;
                asm volatile("ldmatrix.sync.aligned.m8n8.x4.shared.b16 {%0,%1,%2,%3}, [%4];"
                    : "=r"(r0), "=r"(r1), "=r"(r2), "=r"(r3) : "r"(ad));
                MMA(Sa[nn*2],   A[0], A[1], A[2], A[3], r0, r1);
                MMA(Sa[nn*2+1], A[0], A[1], A[2], A[3], r2, r3);
            }
        }

        if (j0 == nkt - 1) {
            int r0 = m0 + w * 16 + g, r1 = r0 + 8, cb = j0 * 128 + t4 * 2;
            #pragma unroll
            for (int j = 0; j < 16; j++) {
                int c0 = cb + j * 8, c1 = c0 + 1;
                if (c0 > r0) Sa[j][0] = -1e30f;
                if (c1 > r0) Sa[j][1] = -1e30f;
                if (c0 > r1) Sa[j][2] = -1e30f;
                if (c1 > r1) Sa[j][3] = -1e30f;
            }
        }

        float mx0 = -1e30f, mx1 = -1e30f;
        #pragma unroll
        for (int j = 0; j < 16; j++) {
            mx0 = fmaxf(mx0, fmaxf(Sa[j][0], Sa[j][1]));
            mx1 = fmaxf(mx1, fmaxf(Sa[j][2], Sa[j][3]));
        }
        mx0 = fmaxf(mx0, __shfl_xor_sync(~0u, mx0, 1));
        mx0 = fmaxf(mx0, __shfl_xor_sync(~0u, mx0, 2));
        mx1 = fmaxf(mx1, __shfl_xor_sync(~0u, mx1, 1));
        mx1 = fmaxf(mx1, __shfl_xor_sync(~0u, mx1, 2));
        float Mn0 = fmaxf(M0, mx0), Mn1 = fmaxf(M1, mx1);
        float sc0 = exp2f(M0 - Mn0), sc1 = exp2f(M1 - Mn1);
        float ls0 = 0.f, ls1 = 0.f;
        #pragma unroll
        for (int j = 0; j < 16; j++) {
            Sa[j][0] = exp2f(Sa[j][0] - Mn0); ls0 += Sa[j][0];
            Sa[j][1] = exp2f(Sa[j][1] - Mn0); ls0 += Sa[j][1];
            Sa[j][2] = exp2f(Sa[j][2] - Mn1); ls1 += Sa[j][2];
            Sa[j][3] = exp2f(Sa[j][3] - Mn1); ls1 += Sa[j][3];
        }
        ls0 += __shfl_xor_sync(~0u, ls0, 1); ls0 += __shfl_xor_sync(~0u, ls0, 2);
        ls1 += __shfl_xor_sync(~0u, ls1, 1); ls1 += __shfl_xor_sync(~0u, ls1, 2);
        L0 = L0 * sc0 + ls0; L1 = L1 * sc1 + ls1;
        M0 = Mn0; M1 = Mn1;
        #pragma unroll
        for (int nf = 0; nf < 8; nf++) {
            O[nf][0] *= sc0; O[nf][1] *= sc0; O[nf][2] *= sc1; O[nf][3] *= sc1;
        }

        #pragma unroll
        for (int tb = 0; tb < 2; tb++) {
            unsigned Ahi[4][4], Alo[4][4];
            #pragma unroll
            for (int f = 0; f < 4; f++) {
                int j = tb * 8 + 2 * f;
                #pragma unroll
                for (int q = 0; q < 2; q++) {
                    float p0 = Sa[j+q][0], p1 = Sa[j+q][1], p2 = Sa[j+q][2], p3 = Sa[j+q][3];
                    __nv_bfloat16 h0,l0,h1,l1,h2,l2,h3,l3;
                    bsplit(p0,h0,l0); bsplit(p1,h1,l1); bsplit(p2,h2,l2); bsplit(p3,h3,l3);
                    Ahi[f][q*2+0] = pack2(__bfloat162float(h0), __bfloat162float(h1));
                    Ahi[f][q*2+1] = pack2(__bfloat162float(h2), __bfloat162float(h3));
                    Alo[f][q*2+0] = pack2(__bfloat162float(l0), __bfloat162float(l1));
                    Alo[f][q*2+1] = pack2(__bfloat162float(l2), __bfloat162float(l3));
                }
            }
            #pragma unroll
            for (int sub = 0; sub < 3; sub++) {
                #pragma unroll
                for (int f = 0; f < 4; f++) {
                    const unsigned* A = (sub == 1) ? Alo[f] : Ahi[f];
                    int kb16 = tb * 12 + sub * 4 + f;
                    #pragma unroll
                    for (int nn = 0; nn < 4; nn++) {
                        int row = kb16 * 16 + (l & 15);
                        int ch  = nn * 2 + (l >> 4);
                        unsigned ad = VsA + row * 128 + ((ch ^ (row & 7)) << 4);
                        unsigned r0, r1, r2, r3;
                        asm volatile("ldmatrix.sync.aligned.m8n8.x4.trans.shared.b16 {%0,%1,%2,%3}, [%4];"
                            : "=r"(r0), "=r"(r1), "=r"(r2), "=r"(r3) : "r"(ad));
                        MMA(O[nn*2],   A[0], A[1], A[2], A[3], r0, r1);
                        MMA(O[nn*2+1], A[0], A[1], A[2], A[3], r2, r3);
                    }
                }
            }
        }
    }

    float i0 = 1.f / L0, i1 = 1.f / L1;
    size_t r0 = (size_t)(b * T + m0 + w * 16 + g) * (3 * E) + 192 * h;
    size_t r1 = r0 + (size_t)8 * (3 * E);
    #pragma unroll
    for (int nf = 0; nf < 8; nf++) {
        #pragma unroll
        for (int e = 0; e < 2; e++) {
            int d = nf * 8 + t4 * 2 + e;
            __nv_bfloat16 hi, lo;
            bsplit(O[nf][e] * i0, hi, lo);
            att3[r0 + d] = hi; att3[r0 + 64 + d] = lo; att3[r0 + 128 + d] = hi;
            bsplit(O[nf][2 + e] * i1, hi, lo);
            att3[r1 + d] = hi; att3[r1 + 64 + d] = lo; att3[r1 + 128 + d] = hi;
        }
    }
}

// ---------------- small kernels ----------------
__global__ void embed_kernel(const int* __restrict__ idx, const float* __restrict__ te,
                             const float* __restrict__ pe, float* __restrict__ x)
{
    int row = blockIdx.x, t = row % T, tok = idx[row];
    const float* a = te + (size_t)tok * E;
    const float* b = pe + (size_t)t * E;
    float* xr = x + (size_t)row * E;
    for (int i = threadIdx.x; i < E; i += blockDim.x) xr[i] = a[i] + b[i];
}

__global__ __launch_bounds__(256)
void layernorm_kernel(const float* __restrict__ x, const float* __restrict__ g,
                      const float* __restrict__ b, __nv_bfloat16* __restrict__ y3)
{
    int row = blockIdx.x, tid = threadIdx.x;
    const float* xr = x + (size_t)row * E;
    float s = 0.f, s2 = 0.f;
    for (int i = tid; i < E; i += 256) { float v = xr[i]; s += v; s2 += v * v; }
    #pragma unroll
    for (int o = 16; o > 0; o >>= 1) {
        s += __shfl_down_sync(~0u, s, o); s2 += __shfl_down_sync(~0u, s2, o);
    }
    __shared__ float ws[8], ws2[8];
    if ((tid & 31) == 0) { ws[tid >> 5] = s; ws2[tid >> 5] = s2; }
    __syncthreads();
    if (tid == 0) {
        float a = 0.f, a2 = 0.f;
        #pragma unroll
        for (int i = 0; i < 8; i++) { a += ws[i]; a2 += ws2[i]; }
        ws[0] = a; ws2[0] = a2;
    }
    __syncthreads();
    float mean = ws[0] / E, var = ws2[0] / E - mean * mean;
    float inv = rsqrtf(var + 1e-5f);
    for (int i = tid; i < E; i += 256) {
        float v = (xr[i] - mean) * inv * g[i] + b[i];
        __nv_bfloat16 hi, lo; bsplit(v, hi, lo);
        size_t base = (size_t)row * (3 * E) + 192 * (i >> 6) + (i & 63);
        y3[base] = hi; y3[base + 64] = lo; y3[base + 128] = hi;
    }
}

__global__ void wsplit_kernel(const float* __restrict__ src, __nv_bfloat16* __restrict__ dst,
                              int N, int dstLD, int colOff)
{
    size_t i = (size_t)blockIdx.x * 256 + threadIdx.x;
    int n = (int)(i % N), k = (int)(i / N);
    float v = src[i];
    __nv_bfloat16 hi, lo; bsplit(v, hi, lo);
    size_t rb = (size_t)(192 * (k >> 6) + (k & 63)) * dstLD + colOff + n;
    dst[rb] = hi; dst[rb + (size_t)64 * dstLD] = hi; dst[rb + (size_t)128 * dstLD] = lo;
}

__global__ void wsplit3_kernel(const float* __restrict__ s0, const float* __restrict__ s1,
                               const float* __restrict__ s2, __nv_bfloat16* __restrict__ dst)
{
    int z = blockIdx.y;
    const float* src = (z == 0) ? s0 : (z == 1) ? s1 : s2;
    size_t i = (size_t)blockIdx.x * 256 + threadIdx.x;
    int n = (int)(i % E), k = (int)(i / E);
    float v = src[i];
    __nv_bfloat16 hi, lo; bsplit(v, hi, lo);
    size_t rb = (size_t)(192 * (k >> 6) + (k & 63)) * (3 * E) + z * E + n;
    dst[rb] = hi; dst[rb + (size_t)64 * 3 * E] = hi; dst[rb + (size_t)128 * 3 * E] = lo;
}

// ---------------- host ----------------
#define SMEMN(BN) (3 * (64 * 64 * 2 + 64 * (BN) * 2))
#define SMEMFL (128 * 192 * 2 + 384 * 64 * 2)

extern "C" void kernel_launch(void* const* d_in, const int* in_sizes, int n_in,
                              void* d_out, int out_size)
{
    const int*   idx     = (const int*)  d_in[0];
    const float* tok_emb = (const float*)d_in[1];
    const float* pos_emb = (const float*)d_in[2];
    const float* wq      = (const float*)d_in[3];
    const float* wk      = (const float*)d_in[4];
    const float* wv      = (const float*)d_in[5];
    const float* wproj   = (const float*)d_in[6];
    const float* bproj   = (const float*)d_in[7];
    const float* ln1_g   = (const float*)d_in[8];
    const float* ln1_b   = (const float*)d_in[9];
    const float* ln2_g   = (const float*)d_in[10];
    const float* ln2_b   = (const float*)d_in[11];
    const float* wfc     = (const float*)d_in[12];
    const float* bfc     = (const float*)d_in[13];
    const float* wpr2    = (const float*)d_in[14];
    const float* bpr2    = (const float*)d_in[15];
    const float* lnf_g   = (const float*)d_in[16];
    const float* lnf_b   = (const float*)d_in[17];
    const float* lm_w    = (const float*)d_in[18];
    const float* lm_b    = (const float*)d_in[19];
    float* out = (float*)d_out;

    cudaFuncSetAttribute(hgemm<128, false>, cudaFuncAttributeMaxDynamicSharedMemorySize, SMEMN(128));
    cudaFuncSetAttribute(hgemm<128, true>,  cudaFuncAttributeMaxDynamicSharedMemorySize, SMEMN(128));
    cudaFuncSetAttribute(flash_kernel, cudaFuncAttributeMaxDynamicSharedMemorySize, SMEMFL);

    float *x, *qkv;
    __nv_bfloat16 *xn3, *att3, *h3, *w3, *lm3;
    cudaGetSymbolAddress((void**)&x, g_x);     cudaGetSymbolAddress((void**)&xn3, g_xn3);
    cudaGetSymbolAddress((void**)&qkv, g_qkv); cudaGetSymbolAddress((void**)&att3, g_att3);
    cudaGetSymbolAddress((void**)&h3, g_h3);   cudaGetSymbolAddress((void**)&w3, g_w3);
    cudaGetSymbolAddress((void**)&lm3, g_lm3);

    embed_kernel<<<ROWS, 256>>>(idx, tok_emb, pos_emb, x);

    for (int l = 0; l < L; l++) {
        const float* wq_l  = wq  + (size_t)l * E * E;
        const float* wk_l  = wk  + (size_t)l * E * E;
        const float* wv_l  = wv  + (size_t)l * E * E;
        const float* wp_l  = wproj + (size_t)l * E * E;
        const float* wfc_l = wfc + (size_t)l * E * F4;
        const float* wp2_l = wpr2 + (size_t)l * F4 * E;

        layernorm_kernel<<<ROWS, 256>>>(x, ln1_g + l * E, ln1_b + l * E, xn3);

        wsplit3_kernel<<<dim3(E * E / 256, 3), 256>>>(wq_l, wk_l, wv_l, w3);
        hgemm<128, false><<<dim3(32, 18), 128, SMEMN(128)>>>(
            xn3, w3, nullptr, nullptr, qkv, nullptr, 3 * E, 3 * E, 3 * E, 3 * E, 0);

        flash_kernel<<<dim3(16, BH), 128, SMEMFL>>>(qkv, att3);

        wsplit_kernel<<<E * E / 256, 256>>>(wp_l, w3, E, E, 0);
        hgemm<128, false><<<dim3(32, 6), 128, SMEMN(128)>>>(
            att3, w3, bproj + l * E, x, x, nullptr, 3 * E, E, E, 3 * E, 0);

        layernorm_kernel<<<ROWS, 256>>>(x, ln2_g + l * E, ln2_b + l * E, xn3);
        wsplit_kernel<<<E * F4 / 256, 256>>>(wfc_l, w3, F4, F4, 0);
        hgemm<128, true><<<dim3(32, 24), 128, SMEMN(128)>>>(
            xn3, w3, bfc + (size_t)l * F4, nullptr, nullptr, h3, 3 * E, F4, 3 * F4, 3 * E, 1);
        wsplit_kernel<<<F4 * E / 256, 256>>>(wp2_l, w3, E, E, 0);
        hgemm<128, false><<<dim3(32, 6), 128, SMEMN(128)>>>(
            h3, w3, bpr2 + l * E, x, x, nullptr, 3 * F4, E, E, 3 * F4, 0);
    }

    layernorm_kernel<<<ROWS, 256>>>(x, lnf_g, lnf_b, xn3);
    wsplit_kernel<<<E * VOCAB / 256, 256>>>(lm_w, lm3, VOCAB, VOCAB, 0);
    hgemm<128, false><<<dim3(32, VOCAB / 128), 128, SMEMN(128)>>>(
        xn3, lm3, lm_b, nullptr, out, nullptr, 3 * E, VOCAB, VOCAB, 3 * E, 0);
}

// round 13
// speedup vs baseline: 1.7549x; 1.0727x over previous
#include <cuda_runtime.h>
#include <cuda_bf16.h>
#include <math.h>

#define BATCH 2
#define T 1024
#define VOCAB 50304
#define E 768
#define L 12
#define H 12
#define HS 64
#define F4 3072
#define ROWS (BATCH * T)
#define BH (BATCH * H)

// ---------------- scratch (2x hi/lo split layout) ----------------
__device__ __align__(128) float          g_x   [ROWS * E];
__device__ __align__(128) __nv_bfloat16  g_xn2 [ROWS * 2 * E];
__device__ __align__(128) float          g_qkv [ROWS * 3 * E];
__device__ __align__(128) __nv_bfloat16  g_att2[ROWS * 2 * E];
__device__ __align__(128) __nv_bfloat16  g_h2  [ROWS * 2 * F4];
__device__ __align__(128) __nv_bfloat16  g_w2  [2 * E * F4];
__device__ __align__(128) __nv_bfloat16  g_lm2 [(size_t)2 * E * VOCAB];

__device__ __forceinline__ unsigned smem_u32(const void* p) {
    unsigned a;
    asm("{ .reg .u64 t; cvta.to.shared.u64 t, %1; cvt.u32.u64 %0, t; }" : "=r"(a) : "l"(p));
    return a;
}
__device__ __forceinline__ void bsplit(float v, __nv_bfloat16& hi, __nv_bfloat16& lo) {
    hi = __float2bfloat16(v);
    lo = __float2bfloat16(v - __bfloat162float(hi));
}
__device__ __forceinline__ unsigned pack2(float a, float b) {
    __nv_bfloat162 p = __floats2bfloat162_rn(a, b);
    return *(unsigned*)&p;
}

#define MMA(acc, a0, a1, a2, a3, b0, b1) \
    asm volatile( \
        "mma.sync.aligned.m16n8k16.row.col.f32.bf16.bf16.f32 " \
        "{%0,%1,%2,%3}, {%4,%5,%6,%7}, {%8,%9}, {%0,%1,%2,%3};" \
        : "+f"((acc)[0]), "+f"((acc)[1]), "+f"((acc)[2]), "+f"((acc)[3]) \
        : "r"(a0), "r"(a1), "r"(a2), "r"(a3), "r"(b0), "r"(b1))

// swizzle for 256B rows: 16 chunks of 16B, XOR low 3 bits with row
#define SWZ16(c, r) ((((c) & 8) | (((c) ^ ((r) & 7)) & 7)) << 4)

// ---------------- bf16x3 GEMM v5: (hi,lo) K2 layout, 3 MMA per frag pair ----
// BM=64, BN=128, 128 threads (2x2 warps, 32x64 tiles). 2 stages of 128 K2-cols.
// C = A[M,K2] @ B[K2,N] with 3-term products: ahi*bhi + alo*bhi + ahi*blo.
template<bool TOUT>
__global__ void __launch_bounds__(128, 2)
hgemm(const __nv_bfloat16* __restrict__ A, const __nv_bfloat16* __restrict__ Bm,
      const float* __restrict__ bias, const float* __restrict__ res,
      float* __restrict__ Cf, __nv_bfloat16* __restrict__ C2,
      int lda, int ldb, int ldc, int K2, int relu)
{
    constexpr int ASTG = 64 * 256;     // 16KB
    constexpr int BSTG = 128 * 256;    // 32KB
    constexpr int STG  = ASTG + BSTG;  // 48KB per stage

    const int m0 = blockIdx.x * 64, n0 = blockIdx.y * 128;

    extern __shared__ __nv_bfloat16 sm[];
    const unsigned sbase = smem_u32(sm);

    const __nv_bfloat16* Ag = A + (size_t)m0 * lda;
    const __nv_bfloat16* Bg = Bm + n0;
    const int kt = K2 / 128;

    const int tid = threadIdx.x;
    const int w = tid >> 5, l = tid & 31;
    const int wm = w >> 1, wn = w & 1;

    auto loadStage = [&](int tt, int s) {
        const unsigned As = sbase + s * STG;
        const unsigned Bs = As + ASTG;
        const __nv_bfloat16* ag = Ag + tt * 128;
        #pragma unroll
        for (int i = 0; i < 8; i++) {
            int id = i * 128 + tid;
            int r = id >> 4, c = id & 15;
            unsigned dst = As + r * 256 + SWZ16(c, r);
            const __nv_bfloat16* src = ag + (size_t)r * lda + c * 8;
            asm volatile("cp.async.cg.shared.global [%0], [%1], 16;" :: "r"(dst), "l"(src));
        }
        const __nv_bfloat16* bg = Bg + (size_t)(tt * 128) * ldb;
        #pragma unroll
        for (int i = 0; i < 16; i++) {
            int id = i * 128 + tid;
            int r = id >> 4, c = id & 15;
            unsigned dst = Bs + r * 256 + SWZ16(c, r);
            const __nv_bfloat16* src = bg + (size_t)r * ldb + c * 8;
            asm volatile("cp.async.cg.shared.global [%0], [%1], 16;" :: "r"(dst), "l"(src));
        }
    };

    loadStage(0, 0);
    asm volatile("cp.async.commit_group;");

    float acc[2][8][4] = {};

    for (int t = 0; t < kt; t++) {
        if (t + 1 < kt) {
            loadStage(t + 1, (t + 1) & 1);
            asm volatile("cp.async.commit_group;");
            asm volatile("cp.async.wait_group 1;");
        } else {
            asm volatile("cp.async.wait_group 0;");
        }
        __syncthreads();

        const unsigned As = sbase + (t & 1) * STG;
        const unsigned Bs = As + ASTG;

        #pragma unroll
        for (int kk = 0; kk < 4; kk++) {
            unsigned fah[2][4], fal[2][4], fbh[8][2], fbl[8][2];
            #pragma unroll
            for (int i = 0; i < 2; i++) {
                int row = wm * 32 + i * 16 + (l & 15);
                int chh = kk * 2 + (l >> 4);
                unsigned ad = As + row * 256 + SWZ16(chh, row);
                asm volatile("ldmatrix.sync.aligned.m8n8.x4.shared.b16 {%0,%1,%2,%3}, [%4];"
                    : "=r"(fah[i][0]), "=r"(fah[i][1]), "=r"(fah[i][2]), "=r"(fah[i][3]) : "r"(ad));
                int chl = chh + 8;
                unsigned al = As + row * 256 + SWZ16(chl, row);
                asm volatile("ldmatrix.sync.aligned.m8n8.x4.shared.b16 {%0,%1,%2,%3}, [%4];"
                    : "=r"(fal[i][0]), "=r"(fal[i][1]), "=r"(fal[i][2]), "=r"(fal[i][3]) : "r"(al));
            }
            #pragma unroll
            for (int p = 0; p < 4; p++) {
                int rh = kk * 16 + (l & 15);
                int ch = wn * 8 + p * 2 + (l >> 4);
                unsigned bd = Bs + rh * 256 + SWZ16(ch, rh);
                unsigned r0, r1, r2, r3;
                asm volatile("ldmatrix.sync.aligned.m8n8.x4.trans.shared.b16 {%0,%1,%2,%3}, [%4];"
                    : "=r"(r0), "=r"(r1), "=r"(r2), "=r"(r3) : "r"(bd));
                fbh[2*p][0] = r0; fbh[2*p][1] = r1; fbh[2*p+1][0] = r2; fbh[2*p+1][1] = r3;
                int rl = rh + 64;
                unsigned bl = Bs + rl * 256 + SWZ16(ch, rl);
                asm volatile("ldmatrix.sync.aligned.m8n8.x4.trans.shared.b16 {%0,%1,%2,%3}, [%4];"
                    : "=r"(r0), "=r"(r1), "=r"(r2), "=r"(r3) : "r"(bl));
                fbl[2*p][0] = r0; fbl[2*p][1] = r1; fbl[2*p+1][0] = r2; fbl[2*p+1][1] = r3;
            }
            #pragma unroll
            for (int i = 0; i < 2; i++)
                #pragma unroll
                for (int j = 0; j < 8; j++) {
                    MMA(acc[i][j], fah[i][0], fah[i][1], fah[i][2], fah[i][3], fbh[j][0], fbh[j][1]);
                    MMA(acc[i][j], fal[i][0], fal[i][1], fal[i][2], fal[i][3], fbh[j][0], fbh[j][1]);
                    MMA(acc[i][j], fah[i][0], fah[i][1], fah[i][2], fah[i][3], fbl[j][0], fbl[j][1]);
                }
        }
        __syncthreads();
    }

    #pragma unroll
    for (int i = 0; i < 2; i++) {
        #pragma unroll
        for (int j = 0; j < 8; j++) {
            #pragma unroll
            for (int half = 0; half < 2; half++) {
                int rr = wm * 32 + i * 16 + (l >> 2) + half * 8;
                int c  = wn * 64 + j * 8 + (l & 3) * 2;
                int cg = n0 + c;
                float v0 = acc[i][j][half * 2 + 0];
                float v1 = acc[i][j][half * 2 + 1];
                size_t ro = (size_t)m0 + rr;
                if (bias) { v0 += bias[cg]; v1 += bias[cg + 1]; }
                if (res)  { v0 += res[ro * ldc + cg]; v1 += res[ro * ldc + cg + 1]; }
                if (relu) { v0 = fmaxf(v0, 0.f); v1 = fmaxf(v1, 0.f); }
                if (TOUT) {
                    int kb = cg >> 6, kr = cg & 63;
                    size_t base = ro * ldc + 128 * kb + kr;
                    __nv_bfloat16 h0, l0, h1, l1;
                    bsplit(v0, h0, l0); bsplit(v1, h1, l1);
                    C2[base]      = h0; C2[base + 1]  = h1;
                    C2[base + 64] = l0; C2[base + 65] = l1;
                } else {
                    Cf[ro * ldc + cg]     = v0;
                    Cf[ro * ldc + cg + 1] = v1;
                }
            }
        }
    }
}

// ---------------- fused flash attention (2x output layout) ----------------
__global__ void __launch_bounds__(128, 2)
flash_kernel(const float* __restrict__ qkv, __nv_bfloat16* __restrict__ att2)
{
    const int m0 = blockIdx.x * 64;
    const int z = blockIdx.y, b = z / H, h = z - b * H;
    const int tid = threadIdx.x, w = tid >> 5, l = tid & 31;
    const int g = l >> 2, t4 = l & 3;

    extern __shared__ __nv_bfloat16 sm[];
    const unsigned KsA = smem_u32(sm);            // [128 tok][192]
    const unsigned VsA = KsA + 128 * 192 * 2;     // [384 k3][64]

    unsigned qhi[4][4], qlo[4][4];
    {
        const float sc = 0.125f * 1.4426950408889634f;
        const float* q0 = qkv + (size_t)(b * T + m0 + w * 16 + g) * (3 * E) + h * 64;
        const float* q1 = q0 + (size_t)8 * (3 * E);
        #pragma unroll
        for (int f = 0; f < 4; f++)
        #pragma unroll
        for (int hv = 0; hv < 2; hv++) {
            int d = f * 16 + hv * 8 + t4 * 2;
            float2 a = *(const float2*)(q0 + d);
            float2 c = *(const float2*)(q1 + d);
            a.x *= sc; a.y *= sc; c.x *= sc; c.y *= sc;
            __nv_bfloat16 ahx, alx, ahy, aly, chx, clx, chy, cly;
            bsplit(a.x, ahx, alx); bsplit(a.y, ahy, aly);
            bsplit(c.x, chx, clx); bsplit(c.y, chy, cly);
            qhi[f][hv * 2 + 0] = pack2(__bfloat162float(ahx), __bfloat162float(ahy));
            qhi[f][hv * 2 + 1] = pack2(__bfloat162float(chx), __bfloat162float(chy));
            qlo[f][hv * 2 + 0] = pack2(__bfloat162float(alx), __bfloat162float(aly));
            qlo[f][hv * 2 + 1] = pack2(__bfloat162float(clx), __bfloat162float(cly));
        }
    }

    float M0 = -1e30f, M1 = -1e30f, L0 = 0.f, L1 = 0.f;
    float O[8][4] = {};

    const int nkt = (m0 + 191) / 128;
    for (int j0 = 0; j0 < nkt; j0++) {
        __syncthreads();
        {
            const float* kg = qkv + (size_t)(b * T + j0 * 128) * (3 * E) + E + h * 64;
            const float* vg = kg + E;
            #pragma unroll
            for (int it = 0; it < 16; it++) {
                int id = it * 128 + tid;
                int tok = id >> 4, dq = (id & 15) * 4;
                float4 v = *(const float4*)(kg + (size_t)tok * (3 * E) + dq);
                __nv_bfloat16 h0,l0,h1,l1,h2,l2,h3,l3;
                bsplit(v.x,h0,l0); bsplit(v.y,h1,l1); bsplit(v.z,h2,l2); bsplit(v.w,h3,l3);
                unsigned hp0 = pack2(__bfloat162float(h0), __bfloat162float(h1));
                unsigned hp1 = pack2(__bfloat162float(h2), __bfloat162float(h3));
                unsigned lp0 = pack2(__bfloat162float(l0), __bfloat162float(l1));
                unsigned lp1 = pack2(__bfloat162float(l2), __bfloat162float(l3));
                unsigned rbase = KsA + tok * 384;
                #pragma unroll
                for (int blk = 0; blk < 3; blk++) {
                    int col = blk * 64 + dq;
                    int c = col >> 3;
                    unsigned ad = rbase + (((c & ~7) | ((c ^ (tok & 7)) & 7)) << 4) + (col & 7) * 2;
                    unsigned v0 = (blk < 2) ? hp0 : lp0;
                    unsigned v1 = (blk < 2) ? hp1 : lp1;
                    asm volatile("st.shared.b32 [%0], %1;" :: "r"(ad), "r"(v0));
                    asm volatile("st.shared.b32 [%0], %1;" :: "r"(ad + 4), "r"(v1));
                }
                float4 vv = *(const float4*)(vg + (size_t)tok * (3 * E) + dq);
                bsplit(vv.x,h0,l0); bsplit(vv.y,h1,l1); bsplit(vv.z,h2,l2); bsplit(vv.w,h3,l3);
                hp0 = pack2(__bfloat162float(h0), __bfloat162float(h1));
                hp1 = pack2(__bfloat162float(h2), __bfloat162float(h3));
                lp0 = pack2(__bfloat162float(l0), __bfloat162float(l1));
                lp1 = pack2(__bfloat162float(l2), __bfloat162float(l3));
                int tb = tok >> 6, tt = tok & 63;
                int c = dq >> 3;
                #pragma unroll
                for (int blk = 0; blk < 3; blk++) {
                    int row = tb * 192 + blk * 64 + tt;
                    unsigned ad = VsA + row * 128 + ((c ^ (row & 7)) << 4) + (dq & 7) * 2;
                    unsigned v0 = (blk < 2) ? hp0 : lp0;
                    unsigned v1 = (blk < 2) ? hp1 : lp1;
                    asm volatile("st.shared.b32 [%0], %1;" :: "r"(ad), "r"(v0));
                    asm volatile("st.shared.b32 [%0], %1;" :: "r"(ad + 4), "r"(v1));
                }
            }
        }
        __syncthreads();

        float Sa[16][4];
        #pragma unroll
        for (int j = 0; j < 16; j++) { Sa[j][0]=0.f; Sa[j][1]=0.f; Sa[j][2]=0.f; Sa[j][3]=0.f; }

        #pragma unroll
        for (int f = 0; f < 12; f++) {
            const unsigned* A = (f < 4) ? qhi[f] : (f < 8) ? qlo[f - 4] : qhi[f - 8];
            #pragma unroll
            for (int nn = 0; nn < 8; nn++) {
                int row = nn * 16 + ((l >> 4) << 3) + (l & 7);
                int ch  = 2 * f + ((l >> 3) & 1);
                unsigned ad = KsA + row * 384 + (((ch & ~7) | ((ch ^ (row & 7)) & 7)) << 4);
                unsigned r0, r1, r2, r3;
                asm volatile("ldmatrix.sync.aligned.m8n8.x4.shared.b16 {%0,%1,%2,%3}, [%4];"
                    : "=r"(r0), "=r"(r1), "=r"(r2), "=r"(r3) : "r"(ad));
                MMA(Sa[nn*2],   A[0], A[1], A[2], A[3], r0, r1);
                MMA(Sa[nn*2+1], A[0], A[1], A[2], A[3], r2, r3);
            }
        }

        if (j0 == nkt - 1) {
            int r0 = m0 + w * 16 + g, r1 = r0 + 8, cb = j0 * 128 + t4 * 2;
            #pragma unroll
            for (int j = 0; j < 16; j++) {
                int c0 = cb + j * 8, c1 = c0 + 1;
                if (c0 > r0) Sa[j][0] = -1e30f;
                if (c1 > r0) Sa[j][1] = -1e30f;
                if (c0 > r1) Sa[j][2] = -1e30f;
                if (c1 > r1) Sa[j][3] = -1e30f;
            }
        }

        float mx0 = -1e30f, mx1 = -1e30f;
        #pragma unroll
        for (int j = 0; j < 16; j++) {
            mx0 = fmaxf(mx0, fmaxf(Sa[j][0], Sa[j][1]));
            mx1 = fmaxf(mx1, fmaxf(Sa[j][2], Sa[j][3]));
        }
        mx0 = fmaxf(mx0, __shfl_xor_sync(~0u, mx0, 1));
        mx0 = fmaxf(mx0, __shfl_xor_sync(~0u, mx0, 2));
        mx1 = fmaxf(mx1, __shfl_xor_sync(~0u, mx1, 1));
        mx1 = fmaxf(mx1, __shfl_xor_sync(~0u, mx1, 2));
        float Mn0 = fmaxf(M0, mx0), Mn1 = fmaxf(M1, mx1);
        float sc0 = exp2f(M0 - Mn0), sc1 = exp2f(M1 - Mn1);
        float ls0 = 0.f, ls1 = 0.f;
        #pragma unroll
        for (int j = 0; j < 16; j++) {
            Sa[j][0] = exp2f(Sa[j][0] - Mn0); ls0 += Sa[j][0];
            Sa[j][1] = exp2f(Sa[j][1] - Mn0); ls0 += Sa[j][1];
            Sa[j][2] = exp2f(Sa[j][2] - Mn1); ls1 += Sa[j][2];
            Sa[j][3] = exp2f(Sa[j][3] - Mn1); ls1 += Sa[j][3];
        }
        ls0 += __shfl_xor_sync(~0u, ls0, 1); ls0 += __shfl_xor_sync(~0u, ls0, 2);
        ls1 += __shfl_xor_sync(~0u, ls1, 1); ls1 += __shfl_xor_sync(~0u, ls1, 2);
        L0 = L0 * sc0 + ls0; L1 = L1 * sc1 + ls1;
        M0 = Mn0; M1 = Mn1;
        #pragma unroll
        for (int nf = 0; nf < 8; nf++) {
            O[nf][0] *= sc0; O[nf][1] *= sc0; O[nf][2] *= sc1; O[nf][3] *= sc1;
        }

        #pragma unroll
        for (int tb = 0; tb < 2; tb++) {
            unsigned Ahi[4][4], Alo[4][4];
            #pragma unroll
            for (int f = 0; f < 4; f++) {
                int j = tb * 8 + 2 * f;
                #pragma unroll
                for (int q = 0; q < 2; q++) {
                    float p0 = Sa[j+q][0], p1 = Sa[j+q][1], p2 = Sa[j+q][2], p3 = Sa[j+q][3];
                    __nv_bfloat16 h0,l0,h1,l1,h2,l2,h3,l3;
                    bsplit(p0,h0,l0); bsplit(p1,h1,l1); bsplit(p2,h2,l2); bsplit(p3,h3,l3);
                    Ahi[f][q*2+0] = pack2(__bfloat162float(h0), __bfloat162float(h1));
                    Ahi[f][q*2+1] = pack2(__bfloat162float(h2), __bfloat162float(h3));
                    Alo[f][q*2+0] = pack2(__bfloat162float(l0), __bfloat162float(l1));
                    Alo[f][q*2+1] = pack2(__bfloat162float(l2), __bfloat162float(l3));
                }
            }
            #pragma unroll
            for (int sub = 0; sub < 3; sub++) {
                #pragma unroll
                for (int f = 0; f < 4; f++) {
                    const unsigned* A = (sub == 1) ? Alo[f] : Ahi[f];
                    int kb16 = tb * 12 + sub * 4 + f;
                    #pragma unroll
                    for (int nn = 0; nn < 4; nn++) {
                        int row = kb16 * 16 + (l & 15);
                        int ch  = nn * 2 + (l >> 4);
                        unsigned ad = VsA + row * 128 + ((ch ^ (row & 7)) << 4);
                        unsigned r0, r1, r2, r3;
                        asm volatile("ldmatrix.sync.aligned.m8n8.x4.trans.shared.b16 {%0,%1,%2,%3}, [%4];"
                            : "=r"(r0), "=r"(r1), "=r"(r2), "=r"(r3) : "r"(ad));
                        MMA(O[nn*2],   A[0], A[1], A[2], A[3], r0, r1);
                        MMA(O[nn*2+1], A[0], A[1], A[2], A[3], r2, r3);
                    }
                }
            }
        }
    }

    float i0 = 1.f / L0, i1 = 1.f / L1;
    size_t r0 = (size_t)(b * T + m0 + w * 16 + g) * (2 * E) + 128 * h;
    size_t r1 = r0 + (size_t)8 * (2 * E);
    #pragma unroll
    for (int nf = 0; nf < 8; nf++) {
        #pragma unroll
        for (int e = 0; e < 2; e++) {
            int d = nf * 8 + t4 * 2 + e;
            __nv_bfloat16 hi, lo;
            bsplit(O[nf][e] * i0, hi, lo);
            att2[r0 + d] = hi; att2[r0 + 64 + d] = lo;
            bsplit(O[nf][2 + e] * i1, hi, lo);
            att2[r1 + d] = hi; att2[r1 + 64 + d] = lo;
        }
    }
}

// ---------------- small kernels ----------------
__global__ void embed_kernel(const int* __restrict__ idx, const float* __restrict__ te,
                             const float* __restrict__ pe, float* __restrict__ x)
{
    int row = blockIdx.x, t = row % T, tok = idx[row];
    const float* a = te + (size_t)tok * E;
    const float* b = pe + (size_t)t * E;
    float* xr = x + (size_t)row * E;
    for (int i = threadIdx.x; i < E; i += blockDim.x) xr[i] = a[i] + b[i];
}

__global__ __launch_bounds__(256)
void layernorm_kernel(const float* __restrict__ x, const float* __restrict__ g,
                      const float* __restrict__ b, __nv_bfloat16* __restrict__ y2)
{
    int row = blockIdx.x, tid = threadIdx.x;
    const float* xr = x + (size_t)row * E;
    float s = 0.f, s2 = 0.f;
    for (int i = tid; i < E; i += 256) { float v = xr[i]; s += v; s2 += v * v; }
    #pragma unroll
    for (int o = 16; o > 0; o >>= 1) {
        s += __shfl_down_sync(~0u, s, o); s2 += __shfl_down_sync(~0u, s2, o);
    }
    __shared__ float ws[8], ws2[8];
    if ((tid & 31) == 0) { ws[tid >> 5] = s; ws2[tid >> 5] = s2; }
    __syncthreads();
    if (tid == 0) {
        float a = 0.f, a2 = 0.f;
        #pragma unroll
        for (int i = 0; i < 8; i++) { a += ws[i]; a2 += ws2[i]; }
        ws[0] = a; ws2[0] = a2;
    }
    __syncthreads();
    float mean = ws[0] / E, var = ws2[0] / E - mean * mean;
    float inv = rsqrtf(var + 1e-5f);
    for (int i = tid; i < E; i += 256) {
        float v = (xr[i] - mean) * inv * g[i] + b[i];
        __nv_bfloat16 hi, lo; bsplit(v, hi, lo);
        size_t base = (size_t)row * (2 * E) + 128 * (i >> 6) + (i & 63);
        y2[base] = hi; y2[base + 64] = lo;
    }
}

// fp32 W[K,N] -> bf16 W2[2K,N]: row 128*(k>>6)+(k&63) hi, +64 lo
__global__ void wsplit_kernel(const float* __restrict__ src, __nv_bfloat16* __restrict__ dst,
                              int N, int colOff)
{
    size_t i = (size_t)blockIdx.x * 256 + threadIdx.x;
    int n = (int)(i % N), k = (int)(i / N);
    float v = src[i];
    __nv_bfloat16 hi, lo; bsplit(v, hi, lo);
    size_t rb = (size_t)(128 * (k >> 6) + (k & 63)) * N + colOff + n;
    dst[rb] = hi; dst[rb + (size_t)64 * N] = lo;
}

__global__ void wsplit3_kernel(const float* __restrict__ s0, const float* __restrict__ s1,
                               const float* __restrict__ s2, __nv_bfloat16* __restrict__ dst)
{
    int z = blockIdx.y;
    const float* src = (z == 0) ? s0 : (z == 1) ? s1 : s2;
    size_t i = (size_t)blockIdx.x * 256 + threadIdx.x;
    int n = (int)(i % E), k = (int)(i / E);
    float v = src[i];
    __nv_bfloat16 hi, lo; bsplit(v, hi, lo);
    size_t rb = (size_t)(128 * (k >> 6) + (k & 63)) * (3 * E) + z * E + n;
    dst[rb] = hi; dst[rb + (size_t)64 * 3 * E] = lo;
}

// ---------------- host ----------------
#define SMEMG (2 * (64 * 256 + 128 * 256))
#define SMEMFL (128 * 192 * 2 + 384 * 64 * 2)

extern "C" void kernel_launch(void* const* d_in, const int* in_sizes, int n_in,
                              void* d_out, int out_size)
{
    const int*   idx     = (const int*)  d_in[0];
    const float* tok_emb = (const float*)d_in[1];
    const float* pos_emb = (const float*)d_in[2];
    const float* wq      = (const float*)d_in[3];
    const float* wk      = (const float*)d_in[4];
    const float* wv      = (const float*)d_in[5];
    const float* wproj   = (const float*)d_in[6];
    const float* bproj   = (const float*)d_in[7];
    const float* ln1_g   = (const float*)d_in[8];
    const float* ln1_b   = (const float*)d_in[9];
    const float* ln2_g   = (const float*)d_in[10];
    const float* ln2_b   = (const float*)d_in[11];
    const float* wfc     = (const float*)d_in[12];
    const float* bfc     = (const float*)d_in[13];
    const float* wpr2    = (const float*)d_in[14];
    const float* bpr2    = (const float*)d_in[15];
    const float* lnf_g   = (const float*)d_in[16];
    const float* lnf_b   = (const float*)d_in[17];
    const float* lm_w    = (const float*)d_in[18];
    const float* lm_b    = (const float*)d_in[19];
    float* out = (float*)d_out;

    cudaFuncSetAttribute(hgemm<false>, cudaFuncAttributeMaxDynamicSharedMemorySize, SMEMG);
    cudaFuncSetAttribute(hgemm<true>,  cudaFuncAttributeMaxDynamicSharedMemorySize, SMEMG);
    cudaFuncSetAttribute(flash_kernel, cudaFuncAttributeMaxDynamicSharedMemorySize, SMEMFL);

    float *x, *qkv;
    __nv_bfloat16 *xn2, *att2, *h2, *w2, *lm2;
    cudaGetSymbolAddress((void**)&x, g_x);     cudaGetSymbolAddress((void**)&xn2, g_xn2);
    cudaGetSymbolAddress((void**)&qkv, g_qkv); cudaGetSymbolAddress((void**)&att2, g_att2);
    cudaGetSymbolAddress((void**)&h2, g_h2);   cudaGetSymbolAddress((void**)&w2, g_w2);
    cudaGetSymbolAddress((void**)&lm2, g_lm2);

    embed_kernel<<<ROWS, 256>>>(idx, tok_emb, pos_emb, x);

    for (int l = 0; l < L; l++) {
        const float* wq_l  = wq  + (size_t)l * E * E;
        const float* wk_l  = wk  + (size_t)l * E * E;
        const float* wv_l  = wv  + (size_t)l * E * E;
        const float* wp_l  = wproj + (size_t)l * E * E;
        const float* wfc_l = wfc + (size_t)l * E * F4;
        const float* wp2_l = wpr2 + (size_t)l * F4 * E;

        layernorm_kernel<<<ROWS, 256>>>(x, ln1_g + l * E, ln1_b + l * E, xn2);

        wsplit3_kernel<<<dim3(E * E / 256, 3), 256>>>(wq_l, wk_l, wv_l, w2);
        hgemm<false><<<dim3(32, 18), 128, SMEMG>>>(
            xn2, w2, nullptr, nullptr, qkv, nullptr, 2 * E, 3 * E, 3 * E, 2 * E, 0);

        flash_kernel<<<dim3(16, BH), 128, SMEMFL>>>(qkv, att2);

        wsplit_kernel<<<E * E / 256, 256>>>(wp_l, w2, E, 0);
        hgemm<false><<<dim3(32, 6), 128, SMEMG>>>(
            att2, w2, bproj + l * E, x, x, nullptr, 2 * E, E, E, 2 * E, 0);

        layernorm_kernel<<<ROWS, 256>>>(x, ln2_g + l * E, ln2_b + l * E, xn2);
        wsplit_kernel<<<E * F4 / 256, 256>>>(wfc_l, w2, F4, 0);
        hgemm<true><<<dim3(32, 24), 128, SMEMG>>>(
            xn2, w2, bfc + (size_t)l * F4, nullptr, nullptr, h2, 2 * E, F4, 2 * F4, 2 * E, 1);
        wsplit_kernel<<<F4 * E / 256, 256>>>(wp2_l, w2, E, 0);
        hgemm<false><<<dim3(32, 6), 128, SMEMG>>>(
            h2, w2, bpr2 + l * E, x, x, nullptr, 2 * F4, E, E, 2 * F4, 0);
    }

    layernorm_kernel<<<ROWS, 256>>>(x, lnf_g, lnf_b, xn2);
    wsplit_kernel<<<E * VOCAB / 256, 256>>>(lm_w, lm2, VOCAB, 0);
    hgemm<false><<<dim3(32, VOCAB / 128), 128, SMEMG>>>(
        xn2, lm2, lm_b, nullptr, out, nullptr, 2 * E, VOCAB, VOCAB, 2 * E, 0);
}